// round 1
// baseline (speedup 1.0000x reference)
#include <cuda_runtime.h>
#include <cuda_bf16.h>
#include <math.h>

// Problem constants
#define BATCH 2
#define LSEQ 2048
#define DMODEL 1024
#define DINNER 2048
#define DSTATE 16
#define DTRANK 128
#define ROWS (BATCH * LSEQ)          // 4096
#define XPROJ_N (DTRANK + 2 * DSTATE) // 160

// Scratch (device globals: allocation-free rule)
__device__ float g_xz[(size_t)ROWS * (2 * DINNER)];  // 64 MB: [4096, 4096] (xb | z)
__device__ float g_u[(size_t)ROWS * DINNER];         // 32 MB
__device__ float g_xdbl[(size_t)ROWS * XPROJ_N];     // 2.6 MB
__device__ float g_dt[(size_t)ROWS * DINNER];        // 32 MB
__device__ float g_y[(size_t)ROWS * DINNER];         // 32 MB

// ---------------------------------------------------------------------------
// SGEMM: C[M,N] = epi( A[M,K](lda) @ B[N,K](ldb)^T )   (both K-major, "NT")
// BM=BN=128, BK=16, 256 threads, 8x8 per thread (two 4x4 quads at +64 stride)
// EPI: 0 = none, 1 = softplus(acc + bias[n])
// ---------------------------------------------------------------------------
template <int EPI>
__global__ __launch_bounds__(256) void sgemm_nt(
    const float* __restrict__ A, const float* __restrict__ B,
    float* __restrict__ C, const float* __restrict__ bias,
    int M, int N, int K, int lda, int ldb, int ldc)
{
    __shared__ float As[16][128];
    __shared__ float Bs[16][128];

    const int tid = threadIdx.x;
    const int m0 = blockIdx.y * 128;
    const int n0 = blockIdx.x * 128;
    const int tx = tid & 15;
    const int ty = tid >> 4;

    const int lr = tid >> 2;        // 0..63
    const int lk = (tid & 3) * 4;   // 0,4,8,12

    float acc[8][8];
#pragma unroll
    for (int i = 0; i < 8; i++)
#pragma unroll
        for (int j = 0; j < 8; j++) acc[i][j] = 0.f;

    for (int k0 = 0; k0 < K; k0 += 16) {
#pragma unroll
        for (int h = 0; h < 2; h++) {
            int row = lr + h * 64;
            float4 v = *(const float4*)(A + (size_t)(m0 + row) * lda + k0 + lk);
            As[lk + 0][row] = v.x; As[lk + 1][row] = v.y;
            As[lk + 2][row] = v.z; As[lk + 3][row] = v.w;
        }
#pragma unroll
        for (int h = 0; h < 2; h++) {
            int row = lr + h * 64;
            float4 v = make_float4(0.f, 0.f, 0.f, 0.f);
            if (n0 + row < N)
                v = *(const float4*)(B + (size_t)(n0 + row) * ldb + k0 + lk);
            Bs[lk + 0][row] = v.x; Bs[lk + 1][row] = v.y;
            Bs[lk + 2][row] = v.z; Bs[lk + 3][row] = v.w;
        }
        __syncthreads();

#pragma unroll
        for (int kk = 0; kk < 16; kk++) {
            float a[8], b[8];
            *(float4*)&a[0] = *(const float4*)&As[kk][ty * 4];
            *(float4*)&a[4] = *(const float4*)&As[kk][ty * 4 + 64];
            *(float4*)&b[0] = *(const float4*)&Bs[kk][tx * 4];
            *(float4*)&b[4] = *(const float4*)&Bs[kk][tx * 4 + 64];
#pragma unroll
            for (int i = 0; i < 8; i++)
#pragma unroll
                for (int j = 0; j < 8; j++)
                    acc[i][j] = fmaf(a[i], b[j], acc[i][j]);
        }
        __syncthreads();
    }

#pragma unroll
    for (int i = 0; i < 8; i++) {
        int grow = m0 + (i >> 2) * 64 + ty * 4 + (i & 3);
#pragma unroll
        for (int j = 0; j < 8; j++) {
            int gcol = n0 + (j >> 2) * 64 + tx * 4 + (j & 3);
            if (gcol < N) {
                float v = acc[i][j];
                if (EPI == 1) {
                    v += bias[gcol];
                    v = (v > 20.f) ? v : log1pf(__expf(v));  // softplus
                }
                C[(size_t)grow * ldc + gcol] = v;
            }
        }
    }
}

// ---------------------------------------------------------------------------
// Causal depthwise conv1d (d_conv=4) + bias + SiLU: xb (cols [0,2048) of xz) -> u
// ---------------------------------------------------------------------------
__global__ __launch_bounds__(256) void conv_silu_kernel(
    const float* __restrict__ xz, const float* __restrict__ w,
    const float* __restrict__ bias, float* __restrict__ u)
{
    int idx = blockIdx.x * blockDim.x + threadIdx.x;
    if (idx >= ROWS * DINNER) return;
    int d = idx & (DINNER - 1);
    int row = idx >> 11;
    int l = row & (LSEQ - 1);

    float w0 = w[d * 4 + 0], w1 = w[d * 4 + 1], w2 = w[d * 4 + 2], w3 = w[d * 4 + 3];
    const float* base = xz + (size_t)row * (2 * DINNER) + d;
    float acc = bias[d] + w3 * base[0];
    if (l >= 1) acc = fmaf(w2, base[-(2 * DINNER)], acc);
    if (l >= 2) acc = fmaf(w1, base[-2 * (2 * DINNER)], acc);
    if (l >= 3) acc = fmaf(w0, base[-3 * (2 * DINNER)], acc);
    // silu
    u[idx] = acc / (1.f + __expf(-acc));
}

// ---------------------------------------------------------------------------
// Selective scan: one thread per (b, d) channel, sequential over L.
// h[n] recurrence in registers; B/C vectors per (b,l) broadcast through L1.
// Fuses +u*D and *silu(z) epilogue; writes y for the final GEMM.
// ---------------------------------------------------------------------------
__global__ __launch_bounds__(128) void scan_kernel(
    const float* __restrict__ u, const float* __restrict__ dt,
    const float* __restrict__ xdbl, const float* __restrict__ xz,
    const float* __restrict__ A_log, const float* __restrict__ Dp,
    float* __restrict__ y)
{
    const int d = blockIdx.x * 128 + threadIdx.x;  // 0..2047
    const int b = blockIdx.y;

    float A[DSTATE];
#pragma unroll
    for (int n = 0; n < DSTATE; n++) A[n] = -__expf(A_log[d * DSTATE + n]);
    const float Dd = Dp[d];

    float h[DSTATE];
#pragma unroll
    for (int n = 0; n < DSTATE; n++) h[n] = 0.f;

    const int rbase = b * LSEQ;
    for (int l = 0; l < LSEQ; l++) {
        const int row = rbase + l;
        const float ut = u[(size_t)row * DINNER + d];
        const float dtt = dt[(size_t)row * DINNER + d];
        const float zt = xz[(size_t)row * (2 * DINNER) + DINNER + d];

        const float4* bc = (const float4*)(xdbl + (size_t)row * XPROJ_N + DTRANK);
        float4 B0 = bc[0], B1 = bc[1], B2 = bc[2], B3 = bc[3];
        float4 C0 = bc[4], C1 = bc[5], C2 = bc[6], C3 = bc[7];
        float Bv[16] = {B0.x, B0.y, B0.z, B0.w, B1.x, B1.y, B1.z, B1.w,
                        B2.x, B2.y, B2.z, B2.w, B3.x, B3.y, B3.z, B3.w};
        float Cv[16] = {C0.x, C0.y, C0.z, C0.w, C1.x, C1.y, C1.z, C1.w,
                        C2.x, C2.y, C2.z, C2.w, C3.x, C3.y, C3.z, C3.w};

        const float dtu = dtt * ut;
        float acc = 0.f;
#pragma unroll
        for (int n = 0; n < DSTATE; n++) {
            float dA = __expf(dtt * A[n]);
            h[n] = fmaf(dA, h[n], dtu * Bv[n]);
            acc = fmaf(h[n], Cv[n], acc);
        }
        float yv = fmaf(ut, Dd, acc);
        float sz = zt / (1.f + __expf(-zt));
        y[(size_t)row * DINNER + d] = yv * sz;
    }
}

// ---------------------------------------------------------------------------
extern "C" void kernel_launch(void* const* d_in, const int* in_sizes, int n_in,
                              void* d_out, int out_size)
{
    const float* x         = (const float*)d_in[0];
    const float* in_proj_w = (const float*)d_in[1];
    const float* conv_w    = (const float*)d_in[2];
    const float* conv_b    = (const float*)d_in[3];
    const float* x_proj_w  = (const float*)d_in[4];
    const float* dt_proj_w = (const float*)d_in[5];
    const float* dt_proj_b = (const float*)d_in[6];
    const float* A_log     = (const float*)d_in[7];
    const float* Dp        = (const float*)d_in[8];
    const float* out_proj_w = (const float*)d_in[9];
    float* out = (float*)d_out;

    float *xz, *u, *xdbl, *dtb, *y;
    cudaGetSymbolAddress((void**)&xz,   g_xz);
    cudaGetSymbolAddress((void**)&u,    g_u);
    cudaGetSymbolAddress((void**)&xdbl, g_xdbl);
    cudaGetSymbolAddress((void**)&dtb,  g_dt);
    cudaGetSymbolAddress((void**)&y,    g_y);

    // 1) xz = x @ in_proj_w^T            [4096, 4096]
    sgemm_nt<0><<<dim3(32, 32), 256>>>(x, in_proj_w, xz, nullptr,
                                       ROWS, 2 * DINNER, DMODEL,
                                       DMODEL, DMODEL, 2 * DINNER);
    // 2) u = silu(causal_conv(xb) + b)   [4096, 2048]
    conv_silu_kernel<<<(ROWS * DINNER) / 256, 256>>>(xz, conv_w, conv_b, u);
    // 3) x_dbl = u @ x_proj_w^T          [4096, 160]
    sgemm_nt<0><<<dim3(2, 32), 256>>>(u, x_proj_w, xdbl, nullptr,
                                      ROWS, XPROJ_N, DINNER,
                                      DINNER, DINNER, XPROJ_N);
    // 4) dt = softplus(dt_in @ dt_proj_w^T + dt_proj_b)   [4096, 2048]
    sgemm_nt<1><<<dim3(16, 32), 256>>>(xdbl, dt_proj_w, dtb, dt_proj_b,
                                       ROWS, DINNER, DTRANK,
                                       XPROJ_N, DTRANK, DINNER);
    // 5) selective scan + D skip + silu(z) gate -> y      [4096, 2048]
    scan_kernel<<<dim3(DINNER / 128, BATCH), 128>>>(u, dtb, xdbl, xz, A_log, Dp, y);
    // 6) out = y @ out_proj_w^T          [4096, 1024]
    sgemm_nt<0><<<dim3(8, 32), 256>>>(y, out_proj_w, out, nullptr,
                                      ROWS, DMODEL, DINNER,
                                      DINNER, DINNER, DMODEL);
}

// round 2
// speedup vs baseline: 1.3699x; 1.3699x over previous
#include <cuda_runtime.h>
#include <cuda_bf16.h>
#include <math.h>
#include <stdint.h>

// Problem constants
#define BATCH 2
#define LSEQ 2048
#define DMODEL 1024
#define DINNER 2048
#define DSTATE 16
#define DTRANK 128
#define ROWS (BATCH * LSEQ)           // 4096
#define XPROJ_N (DTRANK + 2 * DSTATE) // 160

// Scratch (device globals: allocation-free rule)
__device__ float g_xz[(size_t)ROWS * (2 * DINNER)];  // [4096,4096] (xb | z)
__device__ float g_u[(size_t)ROWS * DINNER];
__device__ float g_xdbl[(size_t)ROWS * XPROJ_N];
__device__ float g_dt[(size_t)ROWS * DINNER];
__device__ float g_y[(size_t)ROWS * DINNER];
__device__ float g_xr[(size_t)ROWS * DMODEL];        // tf32-rounded x
__device__ float g_w1[(size_t)(2 * DINNER) * DMODEL];
__device__ float g_w2[(size_t)XPROJ_N * DINNER];
__device__ float g_w3[(size_t)DINNER * DTRANK];
__device__ float g_w4[(size_t)DMODEL * DINNER];

// ---------------------------------------------------------------------------
// helpers
// ---------------------------------------------------------------------------
__device__ __forceinline__ float tf32r(float x) {
    uint32_t r;
    asm("cvt.rna.tf32.f32 %0, %1;" : "=r"(r) : "f"(x));
    return __uint_as_float(r);
}

__device__ __forceinline__ void cp_async16(uint32_t saddr, const void* g) {
    asm volatile("cp.async.cg.shared.global [%0], [%1], 16;\n" :: "r"(saddr), "l"(g));
}
__device__ __forceinline__ void cp_async16_zfill(uint32_t saddr, const void* g, bool pred) {
    int sz = pred ? 16 : 0;
    asm volatile("cp.async.cg.shared.global [%0], [%1], 16, %2;\n" :: "r"(saddr), "l"(g), "r"(sz));
}

// ---------------------------------------------------------------------------
// TF32 tensor-core GEMM:  C[M,N] = epi( A[M,K](lda) @ B[N,K](ldb)^T )
// Both operands K-major ("NT"). Inputs must already be tf32-rounded fp32.
// BM=BN=128, BK=16, 256 threads (8 warps: 2 in M x 4 in N), warp tile 64x32.
// EPI: 0 none; 1 softplus(acc + bias[n]); 2 tf32-round when col < DTRANK.
// ---------------------------------------------------------------------------
#define BK 16
#define SKEW 4
#define LDSM (BK + SKEW)   // 20 floats per row -> conflict-free fragment loads

template <int EPI>
__global__ __launch_bounds__(256) void tf32_gemm(
    const float* __restrict__ A, const float* __restrict__ B,
    float* __restrict__ C, const float* __restrict__ bias,
    int M, int N, int K, int lda, int ldb, int ldc)
{
    __shared__ float As[2][128][LDSM];
    __shared__ float Bs[2][128][LDSM];

    const int tid  = threadIdx.x;
    const int wid  = tid >> 5;
    const int lane = tid & 31;
    const int g    = lane >> 2;   // group id 0..7
    const int tg   = lane & 3;    // thread-in-group 0..3
    const int m0 = blockIdx.y * 128;
    const int n0 = blockIdx.x * 128;
    const int wm = (wid >> 2) * 64;   // 2 warps along M
    const int wn = (wid & 3) * 32;    // 4 warps along N

    float acc[4][4][4];
#pragma unroll
    for (int i = 0; i < 4; i++)
#pragma unroll
        for (int j = 0; j < 4; j++)
#pragma unroll
            for (int r = 0; r < 4; r++) acc[i][j][r] = 0.f;

    // loader: 128 rows x 16 floats per matrix = 512 float4; 256 thr -> 2 each
    const int lrow = tid >> 2;        // 0..63
    const int lc4  = (tid & 3) * 4;   // 0,4,8,12

    auto load_tiles = [&](int s, int k0) {
#pragma unroll
        for (int p = 0; p < 2; p++) {
            int row = p * 64 + lrow;
            uint32_t da = (uint32_t)__cvta_generic_to_shared(&As[s][row][lc4]);
            cp_async16(da, A + (size_t)(m0 + row) * lda + k0 + lc4);
            uint32_t db = (uint32_t)__cvta_generic_to_shared(&Bs[s][row][lc4]);
            int brow = n0 + row;
            const float* src = B + (size_t)(brow < N ? brow : 0) * ldb + k0 + lc4;
            cp_async16_zfill(db, src, brow < N);
        }
    };

    const int nk = K / BK;
    load_tiles(0, 0);
    asm volatile("cp.async.commit_group;\n" ::: "memory");

    int s = 0;
    for (int t = 0; t < nk; t++) {
        asm volatile("cp.async.wait_group 0;\n" ::: "memory");
        __syncthreads();
        if (t + 1 < nk) {
            load_tiles(s ^ 1, (t + 1) * BK);
            asm volatile("cp.async.commit_group;\n" ::: "memory");
        }
#pragma unroll
        for (int ks = 0; ks < 2; ks++) {
            const int kk = ks * 8;
            uint32_t af[4][4];
#pragma unroll
            for (int mi = 0; mi < 4; mi++) {
                int r = wm + mi * 16 + g;
                af[mi][0] = __float_as_uint(As[s][r    ][kk + tg]);
                af[mi][1] = __float_as_uint(As[s][r + 8][kk + tg]);
                af[mi][2] = __float_as_uint(As[s][r    ][kk + tg + 4]);
                af[mi][3] = __float_as_uint(As[s][r + 8][kk + tg + 4]);
            }
            uint32_t bf[4][2];
#pragma unroll
            for (int ni = 0; ni < 4; ni++) {
                int c = wn + ni * 8 + g;
                bf[ni][0] = __float_as_uint(Bs[s][c][kk + tg]);
                bf[ni][1] = __float_as_uint(Bs[s][c][kk + tg + 4]);
            }
#pragma unroll
            for (int mi = 0; mi < 4; mi++)
#pragma unroll
                for (int ni = 0; ni < 4; ni++) {
                    asm volatile(
                        "mma.sync.aligned.m16n8k8.row.col.f32.tf32.tf32.f32 "
                        "{%0,%1,%2,%3}, {%4,%5,%6,%7}, {%8,%9}, {%0,%1,%2,%3};"
                        : "+f"(acc[mi][ni][0]), "+f"(acc[mi][ni][1]),
                          "+f"(acc[mi][ni][2]), "+f"(acc[mi][ni][3])
                        : "r"(af[mi][0]), "r"(af[mi][1]), "r"(af[mi][2]), "r"(af[mi][3]),
                          "r"(bf[ni][0]), "r"(bf[ni][1]));
                }
        }
        __syncthreads();
        s ^= 1;
    }

    // epilogue
#pragma unroll
    for (int mi = 0; mi < 4; mi++) {
        int r0 = m0 + wm + mi * 16 + g;
#pragma unroll
        for (int ni = 0; ni < 4; ni++) {
            int c0 = n0 + wn + ni * 8 + 2 * tg;
#pragma unroll
            for (int rr = 0; rr < 4; rr++) {
                int row = r0 + (rr >> 1) * 8;
                int col = c0 + (rr & 1);
                if (col < N) {
                    float v = acc[mi][ni][rr];
                    if (EPI == 1) {
                        v += bias[col];
                        v = (v > 20.f) ? v : log1pf(__expf(v));
                    } else if (EPI == 2) {
                        if (col < DTRANK) v = tf32r(v);
                    }
                    C[(size_t)row * ldc + col] = v;
                }
            }
        }
    }
}

// ---------------------------------------------------------------------------
// tf32 rounding pass (for x and the 4 weight matrices)
// ---------------------------------------------------------------------------
__global__ __launch_bounds__(256) void round_kernel(
    const float* __restrict__ in, float* __restrict__ out, int n4)
{
    int i = blockIdx.x * blockDim.x + threadIdx.x;
    if (i >= n4) return;
    float4 v = ((const float4*)in)[i];
    v.x = tf32r(v.x); v.y = tf32r(v.y); v.z = tf32r(v.z); v.w = tf32r(v.w);
    ((float4*)out)[i] = v;
}

// ---------------------------------------------------------------------------
// Causal depthwise conv1d (d_conv=4) + bias + SiLU; output tf32-rounded.
// ---------------------------------------------------------------------------
__global__ __launch_bounds__(256) void conv_silu_kernel(
    const float* __restrict__ xz, const float* __restrict__ w,
    const float* __restrict__ bias, float* __restrict__ u)
{
    int idx = blockIdx.x * blockDim.x + threadIdx.x;
    if (idx >= ROWS * DINNER) return;
    int d = idx & (DINNER - 1);
    int row = idx >> 11;
    int l = row & (LSEQ - 1);

    float w0 = w[d * 4 + 0], w1 = w[d * 4 + 1], w2 = w[d * 4 + 2], w3 = w[d * 4 + 3];
    const float* base = xz + (size_t)row * (2 * DINNER) + d;
    float acc = bias[d] + w3 * base[0];
    if (l >= 1) acc = fmaf(w2, base[-(2 * DINNER)], acc);
    if (l >= 2) acc = fmaf(w1, base[-2 * (2 * DINNER)], acc);
    if (l >= 3) acc = fmaf(w0, base[-3 * (2 * DINNER)], acc);
    float s = acc / (1.f + __expf(-acc));
    u[idx] = tf32r(s);
}

// ---------------------------------------------------------------------------
// Selective scan: 4 lanes per (b,d) channel, 4 states each.
// Fast path exploits A[n] = (n+1)*A[0] (verified at runtime): one exp/step.
// Fuses +u*D and *silu(z); output tf32-rounded for the final GEMM.
// ---------------------------------------------------------------------------
__global__ __launch_bounds__(256) void scan_kernel(
    const float* __restrict__ u, const float* __restrict__ dt,
    const float* __restrict__ xdbl, const float* __restrict__ xz,
    const float* __restrict__ A_log, const float* __restrict__ Dp,
    float* __restrict__ y)
{
    const int lane = threadIdx.x & 31;
    const int warp = threadIdx.x >> 5;
    const int sub  = lane & 3;              // which 4-state slice
    const int d    = blockIdx.x * 64 + warp * 8 + (lane >> 2);
    const int b    = blockIdx.y;
    const int nb   = sub * 4;               // first state index

    float A[4];
#pragma unroll
    for (int j = 0; j < 4; j++) A[j] = -__expf(A_log[d * DSTATE + nb + j]);
    const float a0 = -__expf(A_log[d * DSTATE]);  // state-0 coefficient

    bool structured = true;
#pragma unroll
    for (int j = 0; j < 4; j++) {
        float expect = (float)(nb + j + 1) * a0;
        structured = structured && (fabsf(A[j] - expect) <= 1e-4f * (float)(nb + j + 1));
    }

    const float Dd = Dp[d];
    float h0 = 0.f, h1 = 0.f, h2 = 0.f, h3 = 0.f;
    const size_t rb = (size_t)b * LSEQ;

    if (structured) {
        for (int l = 0; l < LSEQ; l++) {
            const size_t row = rb + l;
            const float ut  = u[row * DINNER + d];
            const float dtt = dt[row * DINNER + d];
            const float zt  = xz[row * (2 * DINNER) + DINNER + d];
            const float4 Bv = *(const float4*)(xdbl + row * XPROJ_N + DTRANK + nb);
            const float4 Cv = *(const float4*)(xdbl + row * XPROJ_N + DTRANK + DSTATE + nb);

            float Q  = __expf(dtt * a0);
            float Q2 = Q * Q, Q4 = Q2 * Q2, Q8 = Q4 * Q4;
            float base = Q * ((sub & 1) ? Q4 : 1.f) * ((sub & 2) ? Q8 : 1.f); // Q^(nb+1)
            float dA0 = base, dA1 = dA0 * Q, dA2 = dA1 * Q, dA3 = dA2 * Q;

            float dtu = dtt * ut;
            h0 = fmaf(dA0, h0, dtu * Bv.x);
            h1 = fmaf(dA1, h1, dtu * Bv.y);
            h2 = fmaf(dA2, h2, dtu * Bv.z);
            h3 = fmaf(dA3, h3, dtu * Bv.w);
            float v = h0 * Cv.x;
            v = fmaf(h1, Cv.y, v);
            v = fmaf(h2, Cv.z, v);
            v = fmaf(h3, Cv.w, v);
            v += __shfl_xor_sync(0xffffffffu, v, 1);
            v += __shfl_xor_sync(0xffffffffu, v, 2);
            if (sub == 0) {
                float yv = fmaf(ut, Dd, v);
                float sz = zt / (1.f + __expf(-zt));
                y[row * DINNER + d] = tf32r(yv * sz);
            }
        }
    } else {
        for (int l = 0; l < LSEQ; l++) {
            const size_t row = rb + l;
            const float ut  = u[row * DINNER + d];
            const float dtt = dt[row * DINNER + d];
            const float zt  = xz[row * (2 * DINNER) + DINNER + d];
            const float4 Bv = *(const float4*)(xdbl + row * XPROJ_N + DTRANK + nb);
            const float4 Cv = *(const float4*)(xdbl + row * XPROJ_N + DTRANK + DSTATE + nb);

            float dA0 = __expf(dtt * A[0]);
            float dA1 = __expf(dtt * A[1]);
            float dA2 = __expf(dtt * A[2]);
            float dA3 = __expf(dtt * A[3]);

            float dtu = dtt * ut;
            h0 = fmaf(dA0, h0, dtu * Bv.x);
            h1 = fmaf(dA1, h1, dtu * Bv.y);
            h2 = fmaf(dA2, h2, dtu * Bv.z);
            h3 = fmaf(dA3, h3, dtu * Bv.w);
            float v = h0 * Cv.x;
            v = fmaf(h1, Cv.y, v);
            v = fmaf(h2, Cv.z, v);
            v = fmaf(h3, Cv.w, v);
            v += __shfl_xor_sync(0xffffffffu, v, 1);
            v += __shfl_xor_sync(0xffffffffu, v, 2);
            if (sub == 0) {
                float yv = fmaf(ut, Dd, v);
                float sz = zt / (1.f + __expf(-zt));
                y[row * DINNER + d] = tf32r(yv * sz);
            }
        }
    }
}

// ---------------------------------------------------------------------------
extern "C" void kernel_launch(void* const* d_in, const int* in_sizes, int n_in,
                              void* d_out, int out_size)
{
    const float* x          = (const float*)d_in[0];
    const float* in_proj_w  = (const float*)d_in[1];
    const float* conv_w     = (const float*)d_in[2];
    const float* conv_b     = (const float*)d_in[3];
    const float* x_proj_w   = (const float*)d_in[4];
    const float* dt_proj_w  = (const float*)d_in[5];
    const float* dt_proj_b  = (const float*)d_in[6];
    const float* A_log      = (const float*)d_in[7];
    const float* Dp         = (const float*)d_in[8];
    const float* out_proj_w = (const float*)d_in[9];
    float* out = (float*)d_out;

    float *xz, *u, *xdbl, *dtb, *y, *xr, *w1, *w2, *w3, *w4;
    cudaGetSymbolAddress((void**)&xz,   g_xz);
    cudaGetSymbolAddress((void**)&u,    g_u);
    cudaGetSymbolAddress((void**)&xdbl, g_xdbl);
    cudaGetSymbolAddress((void**)&dtb,  g_dt);
    cudaGetSymbolAddress((void**)&y,    g_y);
    cudaGetSymbolAddress((void**)&xr,   g_xr);
    cudaGetSymbolAddress((void**)&w1,   g_w1);
    cudaGetSymbolAddress((void**)&w2,   g_w2);
    cudaGetSymbolAddress((void**)&w3,   g_w3);
    cudaGetSymbolAddress((void**)&w4,   g_w4);

    // 0) tf32-round GEMM operands
    round_kernel<<<(ROWS * DMODEL / 4 + 255) / 256, 256>>>(x, xr, ROWS * DMODEL / 4);
    round_kernel<<<(2 * DINNER * DMODEL / 4 + 255) / 256, 256>>>(in_proj_w, w1, 2 * DINNER * DMODEL / 4);
    round_kernel<<<(XPROJ_N * DINNER / 4 + 255) / 256, 256>>>(x_proj_w, w2, XPROJ_N * DINNER / 4);
    round_kernel<<<(DINNER * DTRANK / 4 + 255) / 256, 256>>>(dt_proj_w, w3, DINNER * DTRANK / 4);
    round_kernel<<<(DMODEL * DINNER / 4 + 255) / 256, 256>>>(out_proj_w, w4, DMODEL * DINNER / 4);

    // 1) xz = x @ in_proj_w^T            [4096, 4096]
    tf32_gemm<0><<<dim3(32, 32), 256>>>(xr, w1, xz, nullptr,
                                        ROWS, 2 * DINNER, DMODEL,
                                        DMODEL, DMODEL, 2 * DINNER);
    // 2) u = silu(causal_conv(xb) + b)   [4096, 2048]  (tf32-rounded)
    conv_silu_kernel<<<(ROWS * DINNER) / 256, 256>>>(xz, conv_w, conv_b, u);
    // 3) x_dbl = u @ x_proj_w^T          [4096, 160] (dt_in cols tf32-rounded)
    tf32_gemm<2><<<dim3(2, 32), 256>>>(u, w2, xdbl, nullptr,
                                       ROWS, XPROJ_N, DINNER,
                                       DINNER, DINNER, XPROJ_N);
    // 4) dt = softplus(dt_in @ dt_proj_w^T + b)   [4096, 2048]
    tf32_gemm<1><<<dim3(16, 32), 256>>>(xdbl, w3, dtb, dt_proj_b,
                                        ROWS, DINNER, DTRANK,
                                        XPROJ_N, DTRANK, DINNER);
    // 5) selective scan + D skip + silu(z) gate -> y (tf32-rounded)
    scan_kernel<<<dim3(DINNER / 64, BATCH), 256>>>(u, dtb, xdbl, xz, A_log, Dp, y);
    // 6) out = y @ out_proj_w^T          [4096, 1024]
    tf32_gemm<0><<<dim3(8, 32), 256>>>(y, w4, out, nullptr,
                                       ROWS, DMODEL, DINNER,
                                       DINNER, DINNER, DMODEL);
}

// round 3
// speedup vs baseline: 3.5326x; 2.5787x over previous
#include <cuda_runtime.h>
#include <cuda_bf16.h>
#include <math.h>
#include <stdint.h>

// Problem constants
#define BATCH 2
#define LSEQ 2048
#define DMODEL 1024
#define DINNER 2048
#define DSTATE 16
#define DTRANK 128
#define ROWS (BATCH * LSEQ)           // 4096
#define XPROJ_N (DTRANK + 2 * DSTATE) // 160
#define CHUNKS 32
#define CLEN (LSEQ / CHUNKS)          // 64

// Scratch (device globals: allocation-free rule)
__device__ float g_xz[(size_t)ROWS * (2 * DINNER)];  // [4096,4096] (xb | z)
__device__ float g_u[(size_t)ROWS * DINNER];
__device__ float g_xdbl[(size_t)ROWS * XPROJ_N];
__device__ float g_dt[(size_t)ROWS * DINNER];
__device__ float g_y[(size_t)ROWS * DINNER];
__device__ float g_xr[(size_t)ROWS * DMODEL];        // tf32-rounded x
__device__ float g_w1[(size_t)(2 * DINNER) * DMODEL];
__device__ float g_w2[(size_t)XPROJ_N * DINNER];
__device__ float g_w3[(size_t)DINNER * DTRANK];
__device__ float g_w4[(size_t)DMODEL * DINNER];
// chunked-scan state: layout [b][chunk][n][d]
__device__ float g_hpart[(size_t)BATCH * CHUNKS * DSTATE * DINNER];
__device__ float g_hstart[(size_t)BATCH * CHUNKS * DSTATE * DINNER];
__device__ float g_S[(size_t)BATCH * CHUNKS * DINNER];

// ---------------------------------------------------------------------------
// helpers
// ---------------------------------------------------------------------------
__device__ __forceinline__ float tf32r(float x) {
    uint32_t r;
    asm("cvt.rna.tf32.f32 %0, %1;" : "=r"(r) : "f"(x));
    return __uint_as_float(r);
}

__device__ __forceinline__ void cp_async16(uint32_t saddr, const void* g) {
    asm volatile("cp.async.cg.shared.global [%0], [%1], 16;\n" :: "r"(saddr), "l"(g));
}
__device__ __forceinline__ void cp_async16_zfill(uint32_t saddr, const void* g, bool pred) {
    int sz = pred ? 16 : 0;
    asm volatile("cp.async.cg.shared.global [%0], [%1], 16, %2;\n" :: "r"(saddr), "l"(g), "r"(sz));
}

// ---------------------------------------------------------------------------
// TF32 tensor-core GEMM:  C[M,N] = epi( A[M,K](lda) @ B[N,K](ldb)^T )
// ---------------------------------------------------------------------------
#define BK 16
#define SKEW 4
#define LDSMW (BK + SKEW)

template <int EPI>
__global__ __launch_bounds__(256) void tf32_gemm(
    const float* __restrict__ A, const float* __restrict__ B,
    float* __restrict__ C, const float* __restrict__ bias,
    int M, int N, int K, int lda, int ldb, int ldc)
{
    __shared__ float As[2][128][LDSMW];
    __shared__ float Bs[2][128][LDSMW];

    const int tid  = threadIdx.x;
    const int wid  = tid >> 5;
    const int lane = tid & 31;
    const int g    = lane >> 2;
    const int tg   = lane & 3;
    const int m0 = blockIdx.y * 128;
    const int n0 = blockIdx.x * 128;
    const int wm = (wid >> 2) * 64;
    const int wn = (wid & 3) * 32;

    float acc[4][4][4];
#pragma unroll
    for (int i = 0; i < 4; i++)
#pragma unroll
        for (int j = 0; j < 4; j++)
#pragma unroll
            for (int r = 0; r < 4; r++) acc[i][j][r] = 0.f;

    const int lrow = tid >> 2;
    const int lc4  = (tid & 3) * 4;

    auto load_tiles = [&](int s, int k0) {
#pragma unroll
        for (int p = 0; p < 2; p++) {
            int row = p * 64 + lrow;
            uint32_t da = (uint32_t)__cvta_generic_to_shared(&As[s][row][lc4]);
            cp_async16(da, A + (size_t)(m0 + row) * lda + k0 + lc4);
            uint32_t db = (uint32_t)__cvta_generic_to_shared(&Bs[s][row][lc4]);
            int brow = n0 + row;
            const float* src = B + (size_t)(brow < N ? brow : 0) * ldb + k0 + lc4;
            cp_async16_zfill(db, src, brow < N);
        }
    };

    const int nk = K / BK;
    load_tiles(0, 0);
    asm volatile("cp.async.commit_group;\n" ::: "memory");

    int s = 0;
    for (int t = 0; t < nk; t++) {
        asm volatile("cp.async.wait_group 0;\n" ::: "memory");
        __syncthreads();
        if (t + 1 < nk) {
            load_tiles(s ^ 1, (t + 1) * BK);
            asm volatile("cp.async.commit_group;\n" ::: "memory");
        }
#pragma unroll
        for (int ks = 0; ks < 2; ks++) {
            const int kk = ks * 8;
            uint32_t af[4][4];
#pragma unroll
            for (int mi = 0; mi < 4; mi++) {
                int r = wm + mi * 16 + g;
                af[mi][0] = __float_as_uint(As[s][r    ][kk + tg]);
                af[mi][1] = __float_as_uint(As[s][r + 8][kk + tg]);
                af[mi][2] = __float_as_uint(As[s][r    ][kk + tg + 4]);
                af[mi][3] = __float_as_uint(As[s][r + 8][kk + tg + 4]);
            }
            uint32_t bf[4][2];
#pragma unroll
            for (int ni = 0; ni < 4; ni++) {
                int c = wn + ni * 8 + g;
                bf[ni][0] = __float_as_uint(Bs[s][c][kk + tg]);
                bf[ni][1] = __float_as_uint(Bs[s][c][kk + tg + 4]);
            }
#pragma unroll
            for (int mi = 0; mi < 4; mi++)
#pragma unroll
                for (int ni = 0; ni < 4; ni++) {
                    asm volatile(
                        "mma.sync.aligned.m16n8k8.row.col.f32.tf32.tf32.f32 "
                        "{%0,%1,%2,%3}, {%4,%5,%6,%7}, {%8,%9}, {%0,%1,%2,%3};"
                        : "+f"(acc[mi][ni][0]), "+f"(acc[mi][ni][1]),
                          "+f"(acc[mi][ni][2]), "+f"(acc[mi][ni][3])
                        : "r"(af[mi][0]), "r"(af[mi][1]), "r"(af[mi][2]), "r"(af[mi][3]),
                          "r"(bf[ni][0]), "r"(bf[ni][1]));
                }
        }
        __syncthreads();
        s ^= 1;
    }

#pragma unroll
    for (int mi = 0; mi < 4; mi++) {
        int r0 = m0 + wm + mi * 16 + g;
#pragma unroll
        for (int ni = 0; ni < 4; ni++) {
            int c0 = n0 + wn + ni * 8 + 2 * tg;
#pragma unroll
            for (int rr = 0; rr < 4; rr++) {
                int row = r0 + (rr >> 1) * 8;
                int col = c0 + (rr & 1);
                if (col < N) {
                    float v = acc[mi][ni][rr];
                    if (EPI == 1) {
                        v += bias[col];
                        v = (v > 20.f) ? v : log1pf(__expf(v));
                    } else if (EPI == 2) {
                        if (col < DTRANK) v = tf32r(v);
                    }
                    C[(size_t)row * ldc + col] = v;
                }
            }
        }
    }
}

// ---------------------------------------------------------------------------
// tf32 rounding pass
// ---------------------------------------------------------------------------
__global__ __launch_bounds__(256) void round_kernel(
    const float* __restrict__ in, float* __restrict__ out, int n4)
{
    int i = blockIdx.x * blockDim.x + threadIdx.x;
    if (i >= n4) return;
    float4 v = ((const float4*)in)[i];
    v.x = tf32r(v.x); v.y = tf32r(v.y); v.z = tf32r(v.z); v.w = tf32r(v.w);
    ((float4*)out)[i] = v;
}

// ---------------------------------------------------------------------------
// Causal depthwise conv1d (d_conv=4) + bias + SiLU; output tf32-rounded.
// ---------------------------------------------------------------------------
__global__ __launch_bounds__(256) void conv_silu_kernel(
    const float* __restrict__ xz, const float* __restrict__ w,
    const float* __restrict__ bias, float* __restrict__ u)
{
    int idx = blockIdx.x * blockDim.x + threadIdx.x;
    if (idx >= ROWS * DINNER) return;
    int d = idx & (DINNER - 1);
    int row = idx >> 11;
    int l = row & (LSEQ - 1);

    float w0 = w[d * 4 + 0], w1 = w[d * 4 + 1], w2 = w[d * 4 + 2], w3 = w[d * 4 + 3];
    const float* base = xz + (size_t)row * (2 * DINNER) + d;
    float acc = bias[d] + w3 * base[0];
    if (l >= 1) acc = fmaf(w2, base[-(2 * DINNER)], acc);
    if (l >= 2) acc = fmaf(w1, base[-2 * (2 * DINNER)], acc);
    if (l >= 3) acc = fmaf(w0, base[-3 * (2 * DINNER)], acc);
    float s = acc / (1.f + __expf(-acc));
    u[idx] = tf32r(s);
}

// ---------------------------------------------------------------------------
// Chunked selective scan.
// pass1: per (b,d,chunk) thread scans CLEN steps from h=0; emits hpart[16], S=sum(dt).
// combine: per (b,d,n): h_{c+1} = exp(A_n*S_c)*h_c + hpart_c  (exact: the chunk
//          decay product is exp(A_n * sum dt)).
// pass2: re-scan each chunk from its exact h_start; fused y epilogue.
// ---------------------------------------------------------------------------
__device__ __forceinline__ void load_bc16(const float* __restrict__ p, float* v) {
    float4 a = ((const float4*)p)[0], b2 = ((const float4*)p)[1];
    float4 c = ((const float4*)p)[2], e = ((const float4*)p)[3];
    v[0]=a.x; v[1]=a.y; v[2]=a.z; v[3]=a.w;
    v[4]=b2.x; v[5]=b2.y; v[6]=b2.z; v[7]=b2.w;
    v[8]=c.x; v[9]=c.y; v[10]=c.z; v[11]=c.w;
    v[12]=e.x; v[13]=e.y; v[14]=e.z; v[15]=e.w;
}

__global__ __launch_bounds__(128) void scan_pass1(
    const float* __restrict__ u, const float* __restrict__ dt,
    const float* __restrict__ xdbl, const float* __restrict__ A_log,
    float* __restrict__ hpart, float* __restrict__ Ssum)
{
    const int d = blockIdx.x * 128 + threadIdx.x;
    const int c = blockIdx.y;
    const int b = blockIdx.z;

    float A[DSTATE];
    const float a0 = -__expf(A_log[d * DSTATE]);
    bool structured = true;
#pragma unroll
    for (int n = 0; n < DSTATE; n++) {
        A[n] = -__expf(A_log[d * DSTATE + n]);
        structured = structured &&
            (fabsf(A[n] - (float)(n + 1) * a0) <= 1e-4f * (float)(n + 1));
    }

    float h[DSTATE];
#pragma unroll
    for (int n = 0; n < DSTATE; n++) h[n] = 0.f;
    float S = 0.f;

    const int l0 = c * CLEN;
    if (structured) {
        for (int l = l0; l < l0 + CLEN; l++) {
            const size_t row = (size_t)b * LSEQ + l;
            const float ut  = u[row * DINNER + d];
            const float dtt = dt[row * DINNER + d];
            float Bv[16];
            load_bc16(xdbl + row * XPROJ_N + DTRANK, Bv);
            S += dtt;
            const float dtu = dtt * ut;
            const float E = __expf(dtt * a0);
            float dA = E;
#pragma unroll
            for (int n = 0; n < DSTATE; n++) {
                h[n] = fmaf(dA, h[n], dtu * Bv[n]);
                dA *= E;
            }
        }
    } else {
        for (int l = l0; l < l0 + CLEN; l++) {
            const size_t row = (size_t)b * LSEQ + l;
            const float ut  = u[row * DINNER + d];
            const float dtt = dt[row * DINNER + d];
            float Bv[16];
            load_bc16(xdbl + row * XPROJ_N + DTRANK, Bv);
            S += dtt;
            const float dtu = dtt * ut;
#pragma unroll
            for (int n = 0; n < DSTATE; n++)
                h[n] = fmaf(__expf(dtt * A[n]), h[n], dtu * Bv[n]);
        }
    }

    const size_t base = ((size_t)(b * CHUNKS + c) * DSTATE) * DINNER + d;
#pragma unroll
    for (int n = 0; n < DSTATE; n++) hpart[base + (size_t)n * DINNER] = h[n];
    Ssum[(size_t)(b * CHUNKS + c) * DINNER + d] = S;
}

__global__ __launch_bounds__(128) void scan_combine(
    const float* __restrict__ A_log, const float* __restrict__ Ssum,
    const float* __restrict__ hpart, float* __restrict__ hstart)
{
    const int d = blockIdx.x * 128 + threadIdx.x;
    const int n = blockIdx.y;
    const int b = blockIdx.z;
    const float An = -__expf(A_log[d * DSTATE + n]);
    float h = 0.f;
    for (int c = 0; c < CHUNKS; c++) {
        const size_t idx = ((size_t)(b * CHUNKS + c) * DSTATE + n) * DINNER + d;
        hstart[idx] = h;
        const float P = __expf(An * Ssum[(size_t)(b * CHUNKS + c) * DINNER + d]);
        h = fmaf(P, h, hpart[idx]);
    }
}

__global__ __launch_bounds__(128) void scan_pass2(
    const float* __restrict__ u, const float* __restrict__ dt,
    const float* __restrict__ xdbl, const float* __restrict__ xz,
    const float* __restrict__ A_log, const float* __restrict__ Dp,
    const float* __restrict__ hstart, float* __restrict__ y)
{
    const int d = blockIdx.x * 128 + threadIdx.x;
    const int c = blockIdx.y;
    const int b = blockIdx.z;

    float A[DSTATE];
    const float a0 = -__expf(A_log[d * DSTATE]);
    bool structured = true;
#pragma unroll
    for (int n = 0; n < DSTATE; n++) {
        A[n] = -__expf(A_log[d * DSTATE + n]);
        structured = structured &&
            (fabsf(A[n] - (float)(n + 1) * a0) <= 1e-4f * (float)(n + 1));
    }
    const float Dd = Dp[d];

    float h[DSTATE];
    const size_t hbase = ((size_t)(b * CHUNKS + c) * DSTATE) * DINNER + d;
#pragma unroll
    for (int n = 0; n < DSTATE; n++) h[n] = hstart[hbase + (size_t)n * DINNER];

    const int l0 = c * CLEN;
    if (structured) {
        for (int l = l0; l < l0 + CLEN; l++) {
            const size_t row = (size_t)b * LSEQ + l;
            const float ut  = u[row * DINNER + d];
            const float dtt = dt[row * DINNER + d];
            const float zt  = xz[row * (2 * DINNER) + DINNER + d];
            float Bv[16], Cv[16];
            load_bc16(xdbl + row * XPROJ_N + DTRANK, Bv);
            load_bc16(xdbl + row * XPROJ_N + DTRANK + DSTATE, Cv);
            const float dtu = dtt * ut;
            const float E = __expf(dtt * a0);
            float dA = E;
            float acc = 0.f;
#pragma unroll
            for (int n = 0; n < DSTATE; n++) {
                h[n] = fmaf(dA, h[n], dtu * Bv[n]);
                acc = fmaf(h[n], Cv[n], acc);
                dA *= E;
            }
            float yv = fmaf(ut, Dd, acc);
            float sz = zt / (1.f + __expf(-zt));
            y[row * DINNER + d] = tf32r(yv * sz);
        }
    } else {
        for (int l = l0; l < l0 + CLEN; l++) {
            const size_t row = (size_t)b * LSEQ + l;
            const float ut  = u[row * DINNER + d];
            const float dtt = dt[row * DINNER + d];
            const float zt  = xz[row * (2 * DINNER) + DINNER + d];
            float Bv[16], Cv[16];
            load_bc16(xdbl + row * XPROJ_N + DTRANK, Bv);
            load_bc16(xdbl + row * XPROJ_N + DTRANK + DSTATE, Cv);
            const float dtu = dtt * ut;
            float acc = 0.f;
#pragma unroll
            for (int n = 0; n < DSTATE; n++) {
                h[n] = fmaf(__expf(dtt * A[n]), h[n], dtu * Bv[n]);
                acc = fmaf(h[n], Cv[n], acc);
            }
            float yv = fmaf(ut, Dd, acc);
            float sz = zt / (1.f + __expf(-zt));
            y[row * DINNER + d] = tf32r(yv * sz);
        }
    }
}

// ---------------------------------------------------------------------------
extern "C" void kernel_launch(void* const* d_in, const int* in_sizes, int n_in,
                              void* d_out, int out_size)
{
    const float* x          = (const float*)d_in[0];
    const float* in_proj_w  = (const float*)d_in[1];
    const float* conv_w     = (const float*)d_in[2];
    const float* conv_b     = (const float*)d_in[3];
    const float* x_proj_w   = (const float*)d_in[4];
    const float* dt_proj_w  = (const float*)d_in[5];
    const float* dt_proj_b  = (const float*)d_in[6];
    const float* A_log      = (const float*)d_in[7];
    const float* Dp         = (const float*)d_in[8];
    const float* out_proj_w = (const float*)d_in[9];
    float* out = (float*)d_out;

    float *xz, *u, *xdbl, *dtb, *y, *xr, *w1, *w2, *w3, *w4, *hp, *hs, *Ss;
    cudaGetSymbolAddress((void**)&xz,   g_xz);
    cudaGetSymbolAddress((void**)&u,    g_u);
    cudaGetSymbolAddress((void**)&xdbl, g_xdbl);
    cudaGetSymbolAddress((void**)&dtb,  g_dt);
    cudaGetSymbolAddress((void**)&y,    g_y);
    cudaGetSymbolAddress((void**)&xr,   g_xr);
    cudaGetSymbolAddress((void**)&w1,   g_w1);
    cudaGetSymbolAddress((void**)&w2,   g_w2);
    cudaGetSymbolAddress((void**)&w3,   g_w3);
    cudaGetSymbolAddress((void**)&w4,   g_w4);
    cudaGetSymbolAddress((void**)&hp,   g_hpart);
    cudaGetSymbolAddress((void**)&hs,   g_hstart);
    cudaGetSymbolAddress((void**)&Ss,   g_S);

    // 0) tf32-round GEMM operands
    round_kernel<<<(ROWS * DMODEL / 4 + 255) / 256, 256>>>(x, xr, ROWS * DMODEL / 4);
    round_kernel<<<(2 * DINNER * DMODEL / 4 + 255) / 256, 256>>>(in_proj_w, w1, 2 * DINNER * DMODEL / 4);
    round_kernel<<<(XPROJ_N * DINNER / 4 + 255) / 256, 256>>>(x_proj_w, w2, XPROJ_N * DINNER / 4);
    round_kernel<<<(DINNER * DTRANK / 4 + 255) / 256, 256>>>(dt_proj_w, w3, DINNER * DTRANK / 4);
    round_kernel<<<(DMODEL * DINNER / 4 + 255) / 256, 256>>>(out_proj_w, w4, DMODEL * DINNER / 4);

    // 1) xz = x @ in_proj_w^T            [4096, 4096]
    tf32_gemm<0><<<dim3(32, 32), 256>>>(xr, w1, xz, nullptr,
                                        ROWS, 2 * DINNER, DMODEL,
                                        DMODEL, DMODEL, 2 * DINNER);
    // 2) u = silu(causal_conv(xb) + b)   [4096, 2048]
    conv_silu_kernel<<<(ROWS * DINNER) / 256, 256>>>(xz, conv_w, conv_b, u);
    // 3) x_dbl = u @ x_proj_w^T          [4096, 160]
    tf32_gemm<2><<<dim3(2, 32), 256>>>(u, w2, xdbl, nullptr,
                                       ROWS, XPROJ_N, DINNER,
                                       DINNER, DINNER, XPROJ_N);
    // 4) dt = softplus(dt_in @ dt_proj_w^T + b)   [4096, 2048]
    tf32_gemm<1><<<dim3(16, 32), 256>>>(xdbl, w3, dtb, dt_proj_b,
                                        ROWS, DINNER, DTRANK,
                                        XPROJ_N, DTRANK, DINNER);
    // 5) chunked selective scan -> y
    scan_pass1<<<dim3(DINNER / 128, CHUNKS, BATCH), 128>>>(u, dtb, xdbl, A_log, hp, Ss);
    scan_combine<<<dim3(DINNER / 128, DSTATE, BATCH), 128>>>(A_log, Ss, hp, hs);
    scan_pass2<<<dim3(DINNER / 128, CHUNKS, BATCH), 128>>>(u, dtb, xdbl, xz, A_log, Dp, hs, y);
    // 6) out = y @ out_proj_w^T          [4096, 1024]
    tf32_gemm<0><<<dim3(8, 32), 256>>>(y, w4, out, nullptr,
                                       ROWS, DMODEL, DINNER,
                                       DINNER, DINNER, DMODEL);
}

// round 6
// speedup vs baseline: 7.7669x; 2.1987x over previous
#include <cuda_runtime.h>
#include <cuda_fp16.h>
#include <math.h>
#include <stdint.h>

// Problem constants
#define BATCH 2
#define LSEQ 2048
#define DMODEL 1024
#define DINNER 2048
#define DSTATE 16
#define DTRANK 128
#define ROWS (BATCH * LSEQ)           // 4096
#define XPROJ_N (DTRANK + 2 * DSTATE) // 160
#define CHUNKS 32
#define CLEN (LSEQ / CHUNKS)          // 64

// Scratch (device globals: allocation-free rule)
__device__ float  g_xz[(size_t)ROWS * (2 * DINNER)];   // in_proj out (xb | z)
__device__ float  g_u[(size_t)ROWS * DINNER];
__device__ __half g_uh[(size_t)ROWS * DINNER];
__device__ float  g_xdbl[(size_t)ROWS * XPROJ_N];
__device__ __half g_dtin_h[(size_t)ROWS * DTRANK];
__device__ float  g_dt[(size_t)ROWS * DINNER];
__device__ __half g_yh[(size_t)ROWS * DINNER];
__device__ __half g_xh[(size_t)ROWS * DMODEL];
__device__ __half g_w1h[(size_t)(2 * DINNER) * DMODEL];
__device__ __half g_w2h[(size_t)XPROJ_N * DINNER];
__device__ __half g_w3h[(size_t)DINNER * DTRANK];
__device__ __half g_w4h[(size_t)DMODEL * DINNER];
__device__ float  g_hpart[(size_t)BATCH * CHUNKS * DSTATE * DINNER];
__device__ float  g_hstart[(size_t)BATCH * CHUNKS * DSTATE * DINNER];
__device__ float  g_S[(size_t)BATCH * CHUNKS * DINNER];

// ---------------------------------------------------------------------------
// helpers
// ---------------------------------------------------------------------------
__device__ __forceinline__ void cp_async16(uint32_t saddr, const void* g) {
    asm volatile("cp.async.cg.shared.global [%0], [%1], 16;\n" :: "r"(saddr), "l"(g));
}
__device__ __forceinline__ void cp_async16_zfill(uint32_t saddr, const void* g, bool pred) {
    int sz = pred ? 16 : 0;
    asm volatile("cp.async.cg.shared.global [%0], [%1], 16, %2;\n" :: "r"(saddr), "l"(g), "r"(sz));
}

// ---------------------------------------------------------------------------
// fp16 tensor-core GEMM: C[M,N] = epi( A[M,K](lda) @ B[N,K](ldb)^T )
// A,B are __half (K-major), accumulate fp32.
// BM=BN=128, BK=32 halves, 256 threads (8 warps: 2 in M x 4 in N), warp 64x32.
// EPI: 0 plain fp32 C; 1 softplus(acc+bias[col]) fp32; 2 fp32 C + fp16 Ch for col<DTRANK.
// ---------------------------------------------------------------------------
#define BKH 32
#define PADH 8
#define LDH (BKH + PADH)   // 40 halves per row

template <int EPI>
__global__ __launch_bounds__(256) void hgemm_nt(
    const __half* __restrict__ A, const __half* __restrict__ B,
    float* __restrict__ C, const float* __restrict__ bias,
    __half* __restrict__ Ch,
    int M, int N, int K, int lda, int ldb, int ldc)
{
    __shared__ __half As[2][128][LDH];
    __shared__ __half Bs[2][128][LDH];

    const int tid  = threadIdx.x;
    const int wid  = tid >> 5;
    const int lane = tid & 31;
    const int g    = lane >> 2;     // group 0..7
    const int tg   = lane & 3;      // 0..3
    const int m0 = blockIdx.y * 128;
    const int n0 = blockIdx.x * 128;
    const int wm = (wid >> 2) * 64;
    const int wn = (wid & 3) * 32;

    float acc[4][4][4];
#pragma unroll
    for (int i = 0; i < 4; i++)
#pragma unroll
        for (int j = 0; j < 4; j++)
#pragma unroll
            for (int r = 0; r < 4; r++) acc[i][j][r] = 0.f;

    // loader: 128 rows x 64B per tile = 512 x 16B chunks; 256 threads -> 2 each
    auto load_tiles = [&](int s, int k0) {
#pragma unroll
        for (int h = 0; h < 2; h++) {
            int idx = tid + h * 256;          // 0..511
            int row = idx >> 2;
            int ch  = idx & 3;                // 16B chunk = 8 halves
            uint32_t da = (uint32_t)__cvta_generic_to_shared(&As[s][row][ch * 8]);
            cp_async16(da, A + (size_t)(m0 + row) * lda + k0 + ch * 8);
            uint32_t db = (uint32_t)__cvta_generic_to_shared(&Bs[s][row][ch * 8]);
            int brow = n0 + row;
            const __half* src = B + (size_t)(brow < N ? brow : 0) * ldb + k0 + ch * 8;
            cp_async16_zfill(db, src, brow < N);
        }
    };

    const int nk = K / BKH;
    load_tiles(0, 0);
    asm volatile("cp.async.commit_group;\n" ::: "memory");

    int s = 0;
    for (int t = 0; t < nk; t++) {
        asm volatile("cp.async.wait_group 0;\n" ::: "memory");
        __syncthreads();
        if (t + 1 < nk) {
            load_tiles(s ^ 1, (t + 1) * BKH);
            asm volatile("cp.async.commit_group;\n" ::: "memory");
        }
#pragma unroll
        for (int ks = 0; ks < 2; ks++) {
            const int kk = ks * 16;
            uint32_t af[4][4];
#pragma unroll
            for (int mi = 0; mi < 4; mi++) {
                int r = wm + mi * 16 + g;
                af[mi][0] = *(const uint32_t*)&As[s][r    ][kk + 2 * tg];
                af[mi][1] = *(const uint32_t*)&As[s][r + 8][kk + 2 * tg];
                af[mi][2] = *(const uint32_t*)&As[s][r    ][kk + 2 * tg + 8];
                af[mi][3] = *(const uint32_t*)&As[s][r + 8][kk + 2 * tg + 8];
            }
            uint32_t bf[4][2];
#pragma unroll
            for (int ni = 0; ni < 4; ni++) {
                int c = wn + ni * 8 + g;
                bf[ni][0] = *(const uint32_t*)&Bs[s][c][kk + 2 * tg];
                bf[ni][1] = *(const uint32_t*)&Bs[s][c][kk + 2 * tg + 8];
            }
#pragma unroll
            for (int mi = 0; mi < 4; mi++)
#pragma unroll
                for (int ni = 0; ni < 4; ni++) {
                    asm volatile(
                        "mma.sync.aligned.m16n8k16.row.col.f32.f16.f16.f32 "
                        "{%0,%1,%2,%3}, {%4,%5,%6,%7}, {%8,%9}, {%0,%1,%2,%3};"
                        : "+f"(acc[mi][ni][0]), "+f"(acc[mi][ni][1]),
                          "+f"(acc[mi][ni][2]), "+f"(acc[mi][ni][3])
                        : "r"(af[mi][0]), "r"(af[mi][1]), "r"(af[mi][2]), "r"(af[mi][3]),
                          "r"(bf[ni][0]), "r"(bf[ni][1]));
                }
        }
        __syncthreads();
        s ^= 1;
    }

    // epilogue: c0,c1 -> row g cols 2tg,2tg+1 ; c2,c3 -> row g+8
#pragma unroll
    for (int mi = 0; mi < 4; mi++) {
        int r0 = m0 + wm + mi * 16 + g;
#pragma unroll
        for (int ni = 0; ni < 4; ni++) {
            int c0 = n0 + wn + ni * 8 + 2 * tg;
#pragma unroll
            for (int rr = 0; rr < 4; rr++) {
                int row = r0 + (rr >> 1) * 8;
                int col = c0 + (rr & 1);
                if (col < N) {
                    float v = acc[mi][ni][rr];
                    if (EPI == 1) {
                        v += bias[col];
                        v = (v > 20.f) ? v : log1pf(__expf(v));
                    }
                    C[(size_t)row * ldc + col] = v;
                    if (EPI == 2 && col < DTRANK)
                        Ch[(size_t)row * DTRANK + col] = __float2half(v);
                }
            }
        }
    }
}

// ---------------------------------------------------------------------------
// fp32 -> fp16 conversion (8 elements per thread)
// ---------------------------------------------------------------------------
__global__ __launch_bounds__(256) void cvt_half_kernel(
    const float* __restrict__ in, __half* __restrict__ out, int n8)
{
    int i = blockIdx.x * blockDim.x + threadIdx.x;
    if (i >= n8) return;
    const float4* p = (const float4*)in + (size_t)i * 2;
    float4 a = p[0], b = p[1];
    __half2 h[4];
    h[0] = __floats2half2_rn(a.x, a.y);
    h[1] = __floats2half2_rn(a.z, a.w);
    h[2] = __floats2half2_rn(b.x, b.y);
    h[3] = __floats2half2_rn(b.z, b.w);
    ((uint4*)out)[i] = *(uint4*)h;
}

// ---------------------------------------------------------------------------
// Causal depthwise conv1d (d_conv=4) + bias + SiLU -> u (fp32) and u_h (fp16)
// ---------------------------------------------------------------------------
__global__ __launch_bounds__(256) void conv_silu_kernel(
    const float* __restrict__ xz, const float* __restrict__ w,
    const float* __restrict__ bias, float* __restrict__ u,
    __half* __restrict__ uh)
{
    int idx = blockIdx.x * blockDim.x + threadIdx.x;
    if (idx >= ROWS * DINNER) return;
    int d = idx & (DINNER - 1);
    int row = idx >> 11;
    int l = row & (LSEQ - 1);

    float w0 = w[d * 4 + 0], w1 = w[d * 4 + 1], w2 = w[d * 4 + 2], w3 = w[d * 4 + 3];
    const float* base = xz + (size_t)row * (2 * DINNER) + d;
    float acc = bias[d] + w3 * base[0];
    if (l >= 1) acc = fmaf(w2, base[-(2 * DINNER)], acc);
    if (l >= 2) acc = fmaf(w1, base[-2 * (2 * DINNER)], acc);
    if (l >= 3) acc = fmaf(w0, base[-3 * (2 * DINNER)], acc);
    float sact = acc / (1.f + __expf(-acc));
    u[idx] = sact;
    uh[idx] = __float2half(sact);
}

// ---------------------------------------------------------------------------
// Chunked selective scan (exact chunk decomposition via exp(A * sum dt)).
// ---------------------------------------------------------------------------
__device__ __forceinline__ void load_bc16(const float* __restrict__ p, float* v) {
    float4 a = ((const float4*)p)[0], b2 = ((const float4*)p)[1];
    float4 c = ((const float4*)p)[2], e = ((const float4*)p)[3];
    v[0]=a.x; v[1]=a.y; v[2]=a.z; v[3]=a.w;
    v[4]=b2.x; v[5]=b2.y; v[6]=b2.z; v[7]=b2.w;
    v[8]=c.x; v[9]=c.y; v[10]=c.z; v[11]=c.w;
    v[12]=e.x; v[13]=e.y; v[14]=e.z; v[15]=e.w;
}

__global__ __launch_bounds__(128) void scan_pass1(
    const float* __restrict__ u, const float* __restrict__ dt,
    const float* __restrict__ xdbl, const float* __restrict__ A_log,
    float* __restrict__ hpart, float* __restrict__ Ssum)
{
    const int d = blockIdx.x * 128 + threadIdx.x;
    const int c = blockIdx.y;
    const int b = blockIdx.z;

    float A[DSTATE];
    const float a0 = -__expf(A_log[d * DSTATE]);
    bool structured = true;
#pragma unroll
    for (int n = 0; n < DSTATE; n++) {
        A[n] = -__expf(A_log[d * DSTATE + n]);
        structured = structured &&
            (fabsf(A[n] - (float)(n + 1) * a0) <= 1e-4f * (float)(n + 1));
    }

    float h[DSTATE];
#pragma unroll
    for (int n = 0; n < DSTATE; n++) h[n] = 0.f;
    float S = 0.f;

    const int l0 = c * CLEN;
    if (structured) {
        for (int l = l0; l < l0 + CLEN; l++) {
            const size_t row = (size_t)b * LSEQ + l;
            const float ut  = u[row * DINNER + d];
            const float dtt = dt[row * DINNER + d];
            float Bv[16];
            load_bc16(xdbl + row * XPROJ_N + DTRANK, Bv);
            S += dtt;
            const float dtu = dtt * ut;
            const float E = __expf(dtt * a0);
            float dA = E;
#pragma unroll
            for (int n = 0; n < DSTATE; n++) {
                h[n] = fmaf(dA, h[n], dtu * Bv[n]);
                dA *= E;
            }
        }
    } else {
        for (int l = l0; l < l0 + CLEN; l++) {
            const size_t row = (size_t)b * LSEQ + l;
            const float ut  = u[row * DINNER + d];
            const float dtt = dt[row * DINNER + d];
            float Bv[16];
            load_bc16(xdbl + row * XPROJ_N + DTRANK, Bv);
            S += dtt;
            const float dtu = dtt * ut;
#pragma unroll
            for (int n = 0; n < DSTATE; n++)
                h[n] = fmaf(__expf(dtt * A[n]), h[n], dtu * Bv[n]);
        }
    }

    const size_t base = ((size_t)(b * CHUNKS + c) * DSTATE) * DINNER + d;
#pragma unroll
    for (int n = 0; n < DSTATE; n++) hpart[base + (size_t)n * DINNER] = h[n];
    Ssum[(size_t)(b * CHUNKS + c) * DINNER + d] = S;
}

__global__ __launch_bounds__(128) void scan_combine(
    const float* __restrict__ A_log, const float* __restrict__ Ssum,
    const float* __restrict__ hpart, float* __restrict__ hstart)
{
    const int d = blockIdx.x * 128 + threadIdx.x;
    const int n = blockIdx.y;
    const int b = blockIdx.z;
    const float An = -__expf(A_log[d * DSTATE + n]);
    float h = 0.f;
    for (int c = 0; c < CHUNKS; c++) {
        const size_t idx = ((size_t)(b * CHUNKS + c) * DSTATE + n) * DINNER + d;
        hstart[idx] = h;
        const float P = __expf(An * Ssum[(size_t)(b * CHUNKS + c) * DINNER + d]);
        h = fmaf(P, h, hpart[idx]);
    }
}

__global__ __launch_bounds__(128) void scan_pass2(
    const float* __restrict__ u, const float* __restrict__ dt,
    const float* __restrict__ xdbl, const float* __restrict__ xz,
    const float* __restrict__ A_log, const float* __restrict__ Dp,
    const float* __restrict__ hstart, __half* __restrict__ yh)
{
    const int d = blockIdx.x * 128 + threadIdx.x;
    const int c = blockIdx.y;
    const int b = blockIdx.z;

    float A[DSTATE];
    const float a0 = -__expf(A_log[d * DSTATE]);
    bool structured = true;
#pragma unroll
    for (int n = 0; n < DSTATE; n++) {
        A[n] = -__expf(A_log[d * DSTATE + n]);
        structured = structured &&
            (fabsf(A[n] - (float)(n + 1) * a0) <= 1e-4f * (float)(n + 1));
    }
    const float Dd = Dp[d];

    float h[DSTATE];
    const size_t hbase = ((size_t)(b * CHUNKS + c) * DSTATE) * DINNER + d;
#pragma unroll
    for (int n = 0; n < DSTATE; n++) h[n] = hstart[hbase + (size_t)n * DINNER];

    const int l0 = c * CLEN;
    if (structured) {
        for (int l = l0; l < l0 + CLEN; l++) {
            const size_t row = (size_t)b * LSEQ + l;
            const float ut  = u[row * DINNER + d];
            const float dtt = dt[row * DINNER + d];
            const float zt  = xz[row * (2 * DINNER) + DINNER + d];
            float Bv[16], Cv[16];
            load_bc16(xdbl + row * XPROJ_N + DTRANK, Bv);
            load_bc16(xdbl + row * XPROJ_N + DTRANK + DSTATE, Cv);
            const float dtu = dtt * ut;
            const float E = __expf(dtt * a0);
            float dA = E;
            float acc = 0.f;
#pragma unroll
            for (int n = 0; n < DSTATE; n++) {
                h[n] = fmaf(dA, h[n], dtu * Bv[n]);
                acc = fmaf(h[n], Cv[n], acc);
                dA *= E;
            }
            float yv = fmaf(ut, Dd, acc);
            float sz = zt / (1.f + __expf(-zt));
            yh[row * DINNER + d] = __float2half(yv * sz);
        }
    } else {
        for (int l = l0; l < l0 + CLEN; l++) {
            const size_t row = (size_t)b * LSEQ + l;
            const float ut  = u[row * DINNER + d];
            const float dtt = dt[row * DINNER + d];
            const float zt  = xz[row * (2 * DINNER) + DINNER + d];
            float Bv[16], Cv[16];
            load_bc16(xdbl + row * XPROJ_N + DTRANK, Bv);
            load_bc16(xdbl + row * XPROJ_N + DTRANK + DSTATE, Cv);
            const float dtu = dtt * ut;
            float acc = 0.f;
#pragma unroll
            for (int n = 0; n < DSTATE; n++) {
                h[n] = fmaf(__expf(dtt * A[n]), h[n], dtu * Bv[n]);
                acc = fmaf(h[n], Cv[n], acc);
            }
            float yv = fmaf(ut, Dd, acc);
            float sz = zt / (1.f + __expf(-zt));
            yh[row * DINNER + d] = __float2half(yv * sz);
        }
    }
}

// ---------------------------------------------------------------------------
extern "C" void kernel_launch(void* const* d_in, const int* in_sizes, int n_in,
                              void* d_out, int out_size)
{
    const float* x          = (const float*)d_in[0];
    const float* in_proj_w  = (const float*)d_in[1];
    const float* conv_w     = (const float*)d_in[2];
    const float* conv_b     = (const float*)d_in[3];
    const float* x_proj_w   = (const float*)d_in[4];
    const float* dt_proj_w  = (const float*)d_in[5];
    const float* dt_proj_b  = (const float*)d_in[6];
    const float* A_log      = (const float*)d_in[7];
    const float* Dp         = (const float*)d_in[8];
    const float* out_proj_w = (const float*)d_in[9];
    float* out = (float*)d_out;

    float *xz, *u, *xdbl, *dtb, *hp, *hs, *Ss;
    __half *uh, *dtin_h, *yh, *xh, *w1h, *w2h, *w3h, *w4h;
    cudaGetSymbolAddress((void**)&xz,     g_xz);
    cudaGetSymbolAddress((void**)&u,      g_u);
    cudaGetSymbolAddress((void**)&uh,     g_uh);
    cudaGetSymbolAddress((void**)&xdbl,   g_xdbl);
    cudaGetSymbolAddress((void**)&dtin_h, g_dtin_h);
    cudaGetSymbolAddress((void**)&dtb,    g_dt);
    cudaGetSymbolAddress((void**)&yh,     g_yh);
    cudaGetSymbolAddress((void**)&xh,     g_xh);
    cudaGetSymbolAddress((void**)&w1h,    g_w1h);
    cudaGetSymbolAddress((void**)&w2h,    g_w2h);
    cudaGetSymbolAddress((void**)&w3h,    g_w3h);
    cudaGetSymbolAddress((void**)&w4h,    g_w4h);
    cudaGetSymbolAddress((void**)&hp,     g_hpart);
    cudaGetSymbolAddress((void**)&hs,     g_hstart);
    cudaGetSymbolAddress((void**)&Ss,     g_S);

    // 0) fp16 conversions of GEMM operands
    cvt_half_kernel<<<(ROWS * DMODEL / 8 + 255) / 256, 256>>>(x, xh, ROWS * DMODEL / 8);
    cvt_half_kernel<<<(2 * DINNER * DMODEL / 8 + 255) / 256, 256>>>(in_proj_w, w1h, 2 * DINNER * DMODEL / 8);
    cvt_half_kernel<<<(XPROJ_N * DINNER / 8 + 255) / 256, 256>>>(x_proj_w, w2h, XPROJ_N * DINNER / 8);
    cvt_half_kernel<<<(DINNER * DTRANK / 8 + 255) / 256, 256>>>(dt_proj_w, w3h, DINNER * DTRANK / 8);
    cvt_half_kernel<<<(DMODEL * DINNER / 8 + 255) / 256, 256>>>(out_proj_w, w4h, DMODEL * DINNER / 8);

    // 1) xz = x @ in_proj_w^T            [4096, 4096]
    hgemm_nt<0><<<dim3(32, 32), 256>>>(xh, w1h, xz, nullptr, nullptr,
                                       ROWS, 2 * DINNER, DMODEL,
                                       DMODEL, DMODEL, 2 * DINNER);
    // 2) u = silu(causal_conv(xb) + b)   [4096, 2048]  (fp32 + fp16)
    conv_silu_kernel<<<(ROWS * DINNER) / 256, 256>>>(xz, conv_w, conv_b, u, uh);
    // 3) x_dbl = u @ x_proj_w^T          [4096, 160]  (+ fp16 dt_in)
    hgemm_nt<2><<<dim3(2, 32), 256>>>(uh, w2h, xdbl, nullptr, dtin_h,
                                      ROWS, XPROJ_N, DINNER,
                                      DINNER, DINNER, XPROJ_N);
    // 4) dt = softplus(dt_in @ dt_proj_w^T + b)   [4096, 2048]
    hgemm_nt<1><<<dim3(16, 32), 256>>>(dtin_h, w3h, dtb, dt_proj_b, nullptr,
                                       ROWS, DINNER, DTRANK,
                                       DTRANK, DTRANK, DINNER);
    // 5) chunked selective scan -> y (fp16)
    scan_pass1<<<dim3(DINNER / 128, CHUNKS, BATCH), 128>>>(u, dtb, xdbl, A_log, hp, Ss);
    scan_combine<<<dim3(DINNER / 128, DSTATE, BATCH), 128>>>(A_log, Ss, hp, hs);
    scan_pass2<<<dim3(DINNER / 128, CHUNKS, BATCH), 128>>>(u, dtb, xdbl, xz, A_log, Dp, hs, yh);
    // 6) out = y @ out_proj_w^T          [4096, 1024]
    hgemm_nt<0><<<dim3(8, 32), 256>>>(yh, w4h, out, nullptr, nullptr,
                                      ROWS, DMODEL, DINNER,
                                      DINNER, DINNER, DMODEL);
}

// round 7
// speedup vs baseline: 8.6375x; 1.1121x over previous
#include <cuda_runtime.h>
#include <cuda_fp16.h>
#include <math.h>
#include <stdint.h>

// Problem constants
#define BATCH 2
#define LSEQ 2048
#define DMODEL 1024
#define DINNER 2048
#define DSTATE 16
#define DTRANK 128
#define ROWS (BATCH * LSEQ)           // 4096
#define XPROJ_N (DTRANK + 2 * DSTATE) // 160
#define CHUNKS 32
#define CLEN (LSEQ / CHUNKS)          // 64

// Scratch (device globals: allocation-free rule)
__device__ __half g_xzh[(size_t)ROWS * (2 * DINNER)];  // in_proj out (xb | z), fp16
__device__ float  g_u[(size_t)ROWS * DINNER];
__device__ __half g_uh[(size_t)ROWS * DINNER];
__device__ float  g_xdbl[(size_t)ROWS * XPROJ_N];
__device__ __half g_dtin_h[(size_t)ROWS * DTRANK];
__device__ float  g_dt[(size_t)ROWS * DINNER];
__device__ __half g_yh[(size_t)ROWS * DINNER];
__device__ __half g_xh[(size_t)ROWS * DMODEL];
__device__ __half g_w1h[(size_t)(2 * DINNER) * DMODEL];
__device__ __half g_w2h[(size_t)XPROJ_N * DINNER];
__device__ __half g_w3h[(size_t)DINNER * DTRANK];
__device__ __half g_w4h[(size_t)DMODEL * DINNER];
__device__ float  g_hpart[(size_t)BATCH * CHUNKS * DSTATE * DINNER];
__device__ float  g_hstart[(size_t)BATCH * CHUNKS * DSTATE * DINNER];
__device__ float  g_S[(size_t)BATCH * CHUNKS * DINNER];

// ---------------------------------------------------------------------------
// helpers
// ---------------------------------------------------------------------------
__device__ __forceinline__ void cp_async16(uint32_t saddr, const void* g) {
    asm volatile("cp.async.cg.shared.global [%0], [%1], 16;\n" :: "r"(saddr), "l"(g));
}
__device__ __forceinline__ void cp_async16_zfill(uint32_t saddr, const void* g, bool pred) {
    int sz = pred ? 16 : 0;
    asm volatile("cp.async.cg.shared.global [%0], [%1], 16, %2;\n" :: "r"(saddr), "l"(g), "r"(sz));
}
__device__ __forceinline__ void ldsm_x4(uint32_t& r0, uint32_t& r1, uint32_t& r2,
                                        uint32_t& r3, uint32_t addr) {
    asm volatile("ldmatrix.sync.aligned.m8n8.x4.shared.b16 {%0,%1,%2,%3}, [%4];"
                 : "=r"(r0), "=r"(r1), "=r"(r2), "=r"(r3) : "r"(addr));
}

// ---------------------------------------------------------------------------
// fp16 tensor-core GEMM: C[M,N] = epi( A[M,K](lda) @ B[N,K](ldb)^T )
// BM=BN=128, BK=32 halves, 256 threads (2x4 warps, warp tile 64x32),
// double-buffered cp.async, ldmatrix fragment loads.
// EPI: 0 fp32 C; 1 softplus(acc+bias) fp32; 2 fp32 C + fp16 Ch (col<DTRANK);
//      3 fp16 Ch only.
// ---------------------------------------------------------------------------
#define BKH 32
#define PADH 8
#define LDH (BKH + PADH)   // 40 halves/row; 80B stride -> conflict-free ldmatrix

template <int EPI>
__global__ __launch_bounds__(256) void hgemm_nt(
    const __half* __restrict__ A, const __half* __restrict__ B,
    float* __restrict__ C, const float* __restrict__ bias,
    __half* __restrict__ Ch,
    int M, int N, int K, int lda, int ldb, int ldc)
{
    __shared__ __half As[2][128][LDH];
    __shared__ __half Bs[2][128][LDH];

    const int tid  = threadIdx.x;
    const int wid  = tid >> 5;
    const int lane = tid & 31;
    const int g    = lane >> 2;
    const int tg   = lane & 3;
    const int m0 = blockIdx.y * 128;
    const int n0 = blockIdx.x * 128;
    const int wm = (wid >> 2) * 64;
    const int wn = (wid & 3) * 32;

    // ldmatrix per-lane base addresses (stage 0, mi/ni2=0, kk=0)
    const int lrow8 = ((lane >> 3) & 1) * 8 + (lane & 7);
    const int lcol8 = (lane >> 4) * 8;
    const uint32_t aBase = (uint32_t)__cvta_generic_to_shared(&As[0][wm + lrow8][lcol8]);
    const uint32_t bBase = (uint32_t)__cvta_generic_to_shared(&Bs[0][wn + lrow8][lcol8]);
    const uint32_t STG_STRIDE = 128 * LDH * 2;   // bytes per stage
    const uint32_t ROW16 = 16 * LDH * 2;         // 16 rows in bytes

    float acc[4][4][4];
#pragma unroll
    for (int i = 0; i < 4; i++)
#pragma unroll
        for (int j = 0; j < 4; j++)
#pragma unroll
            for (int r = 0; r < 4; r++) acc[i][j][r] = 0.f;

    auto load_tiles = [&](int s, int k0) {
#pragma unroll
        for (int h = 0; h < 2; h++) {
            int idx = tid + h * 256;          // 0..511
            int row = idx >> 2;
            int ch  = idx & 3;                // 16B chunk = 8 halves
            uint32_t da = (uint32_t)__cvta_generic_to_shared(&As[s][row][ch * 8]);
            cp_async16(da, A + (size_t)(m0 + row) * lda + k0 + ch * 8);
            uint32_t db = (uint32_t)__cvta_generic_to_shared(&Bs[s][row][ch * 8]);
            int brow = n0 + row;
            const __half* src = B + (size_t)(brow < N ? brow : 0) * ldb + k0 + ch * 8;
            cp_async16_zfill(db, src, brow < N);
        }
    };

    const int nk = K / BKH;
    load_tiles(0, 0);
    asm volatile("cp.async.commit_group;\n" ::: "memory");

    int s = 0;
    for (int t = 0; t < nk; t++) {
        asm volatile("cp.async.wait_group 0;\n" ::: "memory");
        __syncthreads();
        if (t + 1 < nk) {
            load_tiles(s ^ 1, (t + 1) * BKH);
            asm volatile("cp.async.commit_group;\n" ::: "memory");
        }
        const uint32_t aS = aBase + s * STG_STRIDE;
        const uint32_t bS = bBase + s * STG_STRIDE;
#pragma unroll
        for (int ks = 0; ks < 2; ks++) {
            const uint32_t kkb = ks * 32;     // 16 halves = 32 bytes
            uint32_t af[4][4];
#pragma unroll
            for (int mi = 0; mi < 4; mi++)
                ldsm_x4(af[mi][0], af[mi][1], af[mi][2], af[mi][3],
                        aS + mi * ROW16 + kkb);
            uint32_t bf[4][2];
#pragma unroll
            for (int n2 = 0; n2 < 2; n2++) {
                uint32_t b0, b1, b2, b3;
                ldsm_x4(b0, b1, b2, b3, bS + n2 * ROW16 + kkb);
                bf[2 * n2][0] = b0; bf[2 * n2 + 1][0] = b1;
                bf[2 * n2][1] = b2; bf[2 * n2 + 1][1] = b3;
            }
#pragma unroll
            for (int mi = 0; mi < 4; mi++)
#pragma unroll
                for (int ni = 0; ni < 4; ni++) {
                    asm volatile(
                        "mma.sync.aligned.m16n8k16.row.col.f32.f16.f16.f32 "
                        "{%0,%1,%2,%3}, {%4,%5,%6,%7}, {%8,%9}, {%0,%1,%2,%3};"
                        : "+f"(acc[mi][ni][0]), "+f"(acc[mi][ni][1]),
                          "+f"(acc[mi][ni][2]), "+f"(acc[mi][ni][3])
                        : "r"(af[mi][0]), "r"(af[mi][1]), "r"(af[mi][2]), "r"(af[mi][3]),
                          "r"(bf[ni][0]), "r"(bf[ni][1]));
                }
        }
        __syncthreads();
        s ^= 1;
    }

    // epilogue: acc[..][0,1] -> row r, cols c0,c0+1 ; acc[..][2,3] -> row r+8
#pragma unroll
    for (int mi = 0; mi < 4; mi++) {
        int r0 = m0 + wm + mi * 16 + g;
#pragma unroll
        for (int ni = 0; ni < 4; ni++) {
            int c0 = n0 + wn + ni * 8 + 2 * tg;
            if (c0 >= N) continue;
#pragma unroll
            for (int hh = 0; hh < 2; hh++) {
                int row = r0 + hh * 8;
                float v0 = acc[mi][ni][hh * 2 + 0];
                float v1 = acc[mi][ni][hh * 2 + 1];
                if (EPI == 1) {
                    v0 += bias[c0];     v1 += bias[c0 + 1];
                    v0 = (v0 > 20.f) ? v0 : log1pf(__expf(v0));
                    v1 = (v1 > 20.f) ? v1 : log1pf(__expf(v1));
                }
                if (EPI == 3) {
                    *(__half2*)(Ch + (size_t)row * ldc + c0) = __floats2half2_rn(v0, v1);
                } else {
                    *(float2*)(C + (size_t)row * ldc + c0) = make_float2(v0, v1);
                    if (EPI == 2 && c0 < DTRANK)
                        *(__half2*)(Ch + (size_t)row * DTRANK + c0) = __floats2half2_rn(v0, v1);
                }
            }
        }
    }
}

// ---------------------------------------------------------------------------
// fused fp32 -> fp16 conversion of x + 4 weight matrices (one launch)
// ---------------------------------------------------------------------------
#define NG_X  (ROWS * DMODEL / 8)
#define NG_W1 (2 * DINNER * DMODEL / 8)
#define NG_W2 (XPROJ_N * DINNER / 8)
#define NG_W3 (DINNER * DTRANK / 8)
#define NG_W4 (DMODEL * DINNER / 8)
#define NG_TOT (NG_X + NG_W1 + NG_W2 + NG_W3 + NG_W4)

__device__ __forceinline__ void cvt8(const float* in, __half* out, int i) {
    const float4* p = (const float4*)in + (size_t)i * 2;
    float4 a = p[0], b = p[1];
    __half2 h[4];
    h[0] = __floats2half2_rn(a.x, a.y);
    h[1] = __floats2half2_rn(a.z, a.w);
    h[2] = __floats2half2_rn(b.x, b.y);
    h[3] = __floats2half2_rn(b.z, b.w);
    ((uint4*)out)[i] = *(uint4*)h;
}

__global__ __launch_bounds__(256) void cvt_all_kernel(
    const float* __restrict__ x,  __half* __restrict__ xh,
    const float* __restrict__ w1, __half* __restrict__ w1h,
    const float* __restrict__ w2, __half* __restrict__ w2h,
    const float* __restrict__ w3, __half* __restrict__ w3h,
    const float* __restrict__ w4, __half* __restrict__ w4h)
{
    int i = blockIdx.x * blockDim.x + threadIdx.x;
    if (i < NG_X)                           { cvt8(x, xh, i); return; }
    i -= NG_X;
    if (i < NG_W1)                          { cvt8(w1, w1h, i); return; }
    i -= NG_W1;
    if (i < NG_W2)                          { cvt8(w2, w2h, i); return; }
    i -= NG_W2;
    if (i < NG_W3)                          { cvt8(w3, w3h, i); return; }
    i -= NG_W3;
    if (i < NG_W4)                          { cvt8(w4, w4h, i); }
}

// ---------------------------------------------------------------------------
// Causal depthwise conv1d (d_conv=4) + bias + SiLU -> u (fp32) and u_h (fp16)
// ---------------------------------------------------------------------------
__global__ __launch_bounds__(256) void conv_silu_kernel(
    const __half* __restrict__ xzh, const float* __restrict__ w,
    const float* __restrict__ bias, float* __restrict__ u,
    __half* __restrict__ uh)
{
    int idx = blockIdx.x * blockDim.x + threadIdx.x;
    if (idx >= ROWS * DINNER) return;
    int d = idx & (DINNER - 1);
    int row = idx >> 11;
    int l = row & (LSEQ - 1);

    float w0 = w[d * 4 + 0], w1 = w[d * 4 + 1], w2 = w[d * 4 + 2], w3 = w[d * 4 + 3];
    const __half* base = xzh + (size_t)row * (2 * DINNER) + d;
    float acc = bias[d] + w3 * __half2float(base[0]);
    if (l >= 1) acc = fmaf(w2, __half2float(base[-(2 * DINNER)]), acc);
    if (l >= 2) acc = fmaf(w1, __half2float(base[-2 * (2 * DINNER)]), acc);
    if (l >= 3) acc = fmaf(w0, __half2float(base[-3 * (2 * DINNER)]), acc);
    float sact = acc / (1.f + __expf(-acc));
    u[idx] = sact;
    uh[idx] = __float2half(sact);
}

// ---------------------------------------------------------------------------
// Chunked selective scan (exact chunk decomposition via exp(A * sum dt)).
// ---------------------------------------------------------------------------
__device__ __forceinline__ void load_bc16(const float* __restrict__ p, float* v) {
    float4 a = ((const float4*)p)[0], b2 = ((const float4*)p)[1];
    float4 c = ((const float4*)p)[2], e = ((const float4*)p)[3];
    v[0]=a.x; v[1]=a.y; v[2]=a.z; v[3]=a.w;
    v[4]=b2.x; v[5]=b2.y; v[6]=b2.z; v[7]=b2.w;
    v[8]=c.x; v[9]=c.y; v[10]=c.z; v[11]=c.w;
    v[12]=e.x; v[13]=e.y; v[14]=e.z; v[15]=e.w;
}

__global__ __launch_bounds__(128) void scan_pass1(
    const float* __restrict__ u, const float* __restrict__ dt,
    const float* __restrict__ xdbl, const float* __restrict__ A_log,
    float* __restrict__ hpart, float* __restrict__ Ssum)
{
    const int d = blockIdx.x * 128 + threadIdx.x;
    const int c = blockIdx.y;
    const int b = blockIdx.z;

    float A[DSTATE];
    const float a0 = -__expf(A_log[d * DSTATE]);
    bool structured = true;
#pragma unroll
    for (int n = 0; n < DSTATE; n++) {
        A[n] = -__expf(A_log[d * DSTATE + n]);
        structured = structured &&
            (fabsf(A[n] - (float)(n + 1) * a0) <= 1e-4f * (float)(n + 1));
    }

    float h[DSTATE];
#pragma unroll
    for (int n = 0; n < DSTATE; n++) h[n] = 0.f;
    float S = 0.f;

    const int l0 = c * CLEN;
    if (structured) {
        for (int l = l0; l < l0 + CLEN; l++) {
            const size_t row = (size_t)b * LSEQ + l;
            const float ut  = u[row * DINNER + d];
            const float dtt = dt[row * DINNER + d];
            float Bv[16];
            load_bc16(xdbl + row * XPROJ_N + DTRANK, Bv);
            S += dtt;
            const float dtu = dtt * ut;
            const float E = __expf(dtt * a0);
            float dA = E;
#pragma unroll
            for (int n = 0; n < DSTATE; n++) {
                h[n] = fmaf(dA, h[n], dtu * Bv[n]);
                dA *= E;
            }
        }
    } else {
        for (int l = l0; l < l0 + CLEN; l++) {
            const size_t row = (size_t)b * LSEQ + l;
            const float ut  = u[row * DINNER + d];
            const float dtt = dt[row * DINNER + d];
            float Bv[16];
            load_bc16(xdbl + row * XPROJ_N + DTRANK, Bv);
            S += dtt;
            const float dtu = dtt * ut;
#pragma unroll
            for (int n = 0; n < DSTATE; n++)
                h[n] = fmaf(__expf(dtt * A[n]), h[n], dtu * Bv[n]);
        }
    }

    const size_t base = ((size_t)(b * CHUNKS + c) * DSTATE) * DINNER + d;
#pragma unroll
    for (int n = 0; n < DSTATE; n++) hpart[base + (size_t)n * DINNER] = h[n];
    Ssum[(size_t)(b * CHUNKS + c) * DINNER + d] = S;
}

__global__ __launch_bounds__(128) void scan_combine(
    const float* __restrict__ A_log, const float* __restrict__ Ssum,
    const float* __restrict__ hpart, float* __restrict__ hstart)
{
    const int d = blockIdx.x * 128 + threadIdx.x;
    const int n = blockIdx.y;
    const int b = blockIdx.z;
    const float An = -__expf(A_log[d * DSTATE + n]);
    float h = 0.f;
    for (int c = 0; c < CHUNKS; c++) {
        const size_t idx = ((size_t)(b * CHUNKS + c) * DSTATE + n) * DINNER + d;
        hstart[idx] = h;
        const float P = __expf(An * Ssum[(size_t)(b * CHUNKS + c) * DINNER + d]);
        h = fmaf(P, h, hpart[idx]);
    }
}

__global__ __launch_bounds__(128) void scan_pass2(
    const float* __restrict__ u, const float* __restrict__ dt,
    const float* __restrict__ xdbl, const __half* __restrict__ xzh,
    const float* __restrict__ A_log, const float* __restrict__ Dp,
    const float* __restrict__ hstart, __half* __restrict__ yh)
{
    const int d = blockIdx.x * 128 + threadIdx.x;
    const int c = blockIdx.y;
    const int b = blockIdx.z;

    float A[DSTATE];
    const float a0 = -__expf(A_log[d * DSTATE]);
    bool structured = true;
#pragma unroll
    for (int n = 0; n < DSTATE; n++) {
        A[n] = -__expf(A_log[d * DSTATE + n]);
        structured = structured &&
            (fabsf(A[n] - (float)(n + 1) * a0) <= 1e-4f * (float)(n + 1));
    }
    const float Dd = Dp[d];

    float h[DSTATE];
    const size_t hbase = ((size_t)(b * CHUNKS + c) * DSTATE) * DINNER + d;
#pragma unroll
    for (int n = 0; n < DSTATE; n++) h[n] = hstart[hbase + (size_t)n * DINNER];

    const int l0 = c * CLEN;
    if (structured) {
        for (int l = l0; l < l0 + CLEN; l++) {
            const size_t row = (size_t)b * LSEQ + l;
            const float ut  = u[row * DINNER + d];
            const float dtt = dt[row * DINNER + d];
            const float zt  = __half2float(xzh[row * (2 * DINNER) + DINNER + d]);
            float Bv[16], Cv[16];
            load_bc16(xdbl + row * XPROJ_N + DTRANK, Bv);
            load_bc16(xdbl + row * XPROJ_N + DTRANK + DSTATE, Cv);
            const float dtu = dtt * ut;
            const float E = __expf(dtt * a0);
            float dA = E;
            float acc = 0.f;
#pragma unroll
            for (int n = 0; n < DSTATE; n++) {
                h[n] = fmaf(dA, h[n], dtu * Bv[n]);
                acc = fmaf(h[n], Cv[n], acc);
                dA *= E;
            }
            float yv = fmaf(ut, Dd, acc);
            float sz = zt / (1.f + __expf(-zt));
            yh[row * DINNER + d] = __float2half(yv * sz);
        }
    } else {
        for (int l = l0; l < l0 + CLEN; l++) {
            const size_t row = (size_t)b * LSEQ + l;
            const float ut  = u[row * DINNER + d];
            const float dtt = dt[row * DINNER + d];
            const float zt  = __half2float(xzh[row * (2 * DINNER) + DINNER + d]);
            float Bv[16], Cv[16];
            load_bc16(xdbl + row * XPROJ_N + DTRANK, Bv);
            load_bc16(xdbl + row * XPROJ_N + DTRANK + DSTATE, Cv);
            const float dtu = dtt * ut;
            float acc = 0.f;
#pragma unroll
            for (int n = 0; n < DSTATE; n++) {
                h[n] = fmaf(__expf(dtt * A[n]), h[n], dtu * Bv[n]);
                acc = fmaf(h[n], Cv[n], acc);
            }
            float yv = fmaf(ut, Dd, acc);
            float sz = zt / (1.f + __expf(-zt));
            yh[row * DINNER + d] = __float2half(yv * sz);
        }
    }
}

// ---------------------------------------------------------------------------
extern "C" void kernel_launch(void* const* d_in, const int* in_sizes, int n_in,
                              void* d_out, int out_size)
{
    const float* x          = (const float*)d_in[0];
    const float* in_proj_w  = (const float*)d_in[1];
    const float* conv_w     = (const float*)d_in[2];
    const float* conv_b     = (const float*)d_in[3];
    const float* x_proj_w   = (const float*)d_in[4];
    const float* dt_proj_w  = (const float*)d_in[5];
    const float* dt_proj_b  = (const float*)d_in[6];
    const float* A_log      = (const float*)d_in[7];
    const float* Dp         = (const float*)d_in[8];
    const float* out_proj_w = (const float*)d_in[9];
    float* out = (float*)d_out;

    float *u, *xdbl, *dtb, *hp, *hs, *Ss;
    __half *xzh, *uh, *dtin_h, *yh, *xh, *w1h, *w2h, *w3h, *w4h;
    cudaGetSymbolAddress((void**)&xzh,    g_xzh);
    cudaGetSymbolAddress((void**)&u,      g_u);
    cudaGetSymbolAddress((void**)&uh,     g_uh);
    cudaGetSymbolAddress((void**)&xdbl,   g_xdbl);
    cudaGetSymbolAddress((void**)&dtin_h, g_dtin_h);
    cudaGetSymbolAddress((void**)&dtb,    g_dt);
    cudaGetSymbolAddress((void**)&yh,     g_yh);
    cudaGetSymbolAddress((void**)&xh,     g_xh);
    cudaGetSymbolAddress((void**)&w1h,    g_w1h);
    cudaGetSymbolAddress((void**)&w2h,    g_w2h);
    cudaGetSymbolAddress((void**)&w3h,    g_w3h);
    cudaGetSymbolAddress((void**)&w4h,    g_w4h);
    cudaGetSymbolAddress((void**)&hp,     g_hpart);
    cudaGetSymbolAddress((void**)&hs,     g_hstart);
    cudaGetSymbolAddress((void**)&Ss,     g_S);

    // 0) fused fp16 conversion of x + all weights (one launch)
    cvt_all_kernel<<<(NG_TOT + 255) / 256, 256>>>(x, xh, in_proj_w, w1h,
                                                  x_proj_w, w2h, dt_proj_w, w3h,
                                                  out_proj_w, w4h);

    // 1) xz = x @ in_proj_w^T -> fp16 [4096, 4096]
    hgemm_nt<3><<<dim3(32, 32), 256>>>(xh, w1h, nullptr, nullptr, xzh,
                                       ROWS, 2 * DINNER, DMODEL,
                                       DMODEL, DMODEL, 2 * DINNER);
    // 2) u = silu(causal_conv(xb) + b)   [4096, 2048]  (fp32 + fp16)
    conv_silu_kernel<<<(ROWS * DINNER) / 256, 256>>>(xzh, conv_w, conv_b, u, uh);
    // 3) x_dbl = u @ x_proj_w^T          [4096, 160]  (+ fp16 dt_in)
    hgemm_nt<2><<<dim3(2, 32), 256>>>(uh, w2h, xdbl, nullptr, dtin_h,
                                      ROWS, XPROJ_N, DINNER,
                                      DINNER, DINNER, XPROJ_N);
    // 4) dt = softplus(dt_in @ dt_proj_w^T + b)   [4096, 2048]
    hgemm_nt<1><<<dim3(16, 32), 256>>>(dtin_h, w3h, dtb, dt_proj_b, nullptr,
                                       ROWS, DINNER, DTRANK,
                                       DTRANK, DTRANK, DINNER);
    // 5) chunked selective scan -> y (fp16)
    scan_pass1<<<dim3(DINNER / 128, CHUNKS, BATCH), 128>>>(u, dtb, xdbl, A_log, hp, Ss);
    scan_combine<<<dim3(DINNER / 128, DSTATE, BATCH), 128>>>(A_log, Ss, hp, hs);
    scan_pass2<<<dim3(DINNER / 128, CHUNKS, BATCH), 128>>>(u, dtb, xdbl, xzh, A_log, Dp, hs, yh);
    // 6) out = y @ out_proj_w^T          [4096, 1024]
    hgemm_nt<0><<<dim3(8, 32), 256>>>(yh, w4h, out, nullptr, nullptr,
                                      ROWS, DMODEL, DINNER,
                                      DINNER, DINNER, DMODEL);
}

// round 8
// speedup vs baseline: 9.1343x; 1.0575x over previous
#include <cuda_runtime.h>
#include <cuda_fp16.h>
#include <math.h>
#include <stdint.h>

// Problem constants
#define BATCH 2
#define LSEQ 2048
#define DMODEL 1024
#define DINNER 2048
#define DSTATE 16
#define DTRANK 128
#define ROWS (BATCH * LSEQ)           // 4096
#define XPROJ_N (DTRANK + 2 * DSTATE) // 160
#define CHUNKS 32
#define CLEN (LSEQ / CHUNKS)          // 64
#define KSPLIT 4
#define XPN (ROWS * XPROJ_N)          // 655360

// Scratch (device globals: allocation-free rule)
__device__ __half g_xzh[(size_t)ROWS * (2 * DINNER)];  // in_proj out (xb | z), fp16
__device__ float  g_u[(size_t)ROWS * DINNER];
__device__ __half g_uh[(size_t)ROWS * DINNER];
__device__ float  g_xdbl[(size_t)ROWS * XPROJ_N];
__device__ float  g_xp4[(size_t)KSPLIT * XPN];         // x_proj split-K partials
__device__ __half g_dtin_h[(size_t)ROWS * DTRANK];
__device__ float  g_dt[(size_t)ROWS * DINNER];
__device__ __half g_yh[(size_t)ROWS * DINNER];
__device__ __half g_xh[(size_t)ROWS * DMODEL];
__device__ __half g_w1h[(size_t)(2 * DINNER) * DMODEL];
__device__ __half g_w2h[(size_t)XPROJ_N * DINNER];
__device__ __half g_w3h[(size_t)DINNER * DTRANK];
__device__ __half g_w4h[(size_t)DMODEL * DINNER];
__device__ float  g_hpart[(size_t)BATCH * CHUNKS * DSTATE * DINNER];
__device__ float  g_hstart[(size_t)BATCH * CHUNKS * DSTATE * DINNER];
__device__ float  g_S[(size_t)BATCH * CHUNKS * DINNER];

// ---------------------------------------------------------------------------
// helpers
// ---------------------------------------------------------------------------
__device__ __forceinline__ void cp_async16(uint32_t saddr, const void* g) {
    asm volatile("cp.async.cg.shared.global [%0], [%1], 16;\n" :: "r"(saddr), "l"(g));
}
__device__ __forceinline__ void cp_async16_zfill(uint32_t saddr, const void* g, bool pred) {
    int sz = pred ? 16 : 0;
    asm volatile("cp.async.cg.shared.global [%0], [%1], 16, %2;\n" :: "r"(saddr), "l"(g), "r"(sz));
}
__device__ __forceinline__ void ldsm_x4(uint32_t& r0, uint32_t& r1, uint32_t& r2,
                                        uint32_t& r3, uint32_t addr) {
    asm volatile("ldmatrix.sync.aligned.m8n8.x4.shared.b16 {%0,%1,%2,%3}, [%4];"
                 : "=r"(r0), "=r"(r1), "=r"(r2), "=r"(r3) : "r"(addr));
}

// ---------------------------------------------------------------------------
// fp16 tensor-core GEMM: C[M,N] = epi( A[M,K](lda) @ B[N,K](ldb)^T )
// BM=BN=128, BK=32 halves, 256 threads (2x4 warps, warp tile 64x32).
// 3-stage cp.async pipeline (wait_group 1), ldmatrix fragment loads.
// blockIdx.z selects a K-split slice (A/B advanced by z*K; K = per-slice span).
// EPI: 0 fp32 C; 1 softplus(acc+bias) fp32; 3 fp16 Ch only;
//      4 split-K fp32 partial to C + z*M*ldc.
// ---------------------------------------------------------------------------
#define BKH 32
#define PADH 8
#define LDH (BKH + PADH)   // 40 halves/row; 80B stride -> conflict-free ldmatrix
#define HSMEM_BYTES (6 * 128 * LDH * 2)   // 3 stages x (A+B) = 61440 B

template <int EPI>
__global__ __launch_bounds__(256) void hgemm_nt(
    const __half* __restrict__ A, const __half* __restrict__ B,
    float* __restrict__ C, const float* __restrict__ bias,
    __half* __restrict__ Ch,
    int M, int N, int K, int lda, int ldb, int ldc)
{
    extern __shared__ __half sh[];
    __half (*As)[128][LDH] = (__half(*)[128][LDH])sh;
    __half (*Bs)[128][LDH] = (__half(*)[128][LDH])(sh + 3 * 128 * LDH);

    const int tid  = threadIdx.x;
    const int wid  = tid >> 5;
    const int lane = tid & 31;
    const int g    = lane >> 2;
    const int tg   = lane & 3;
    const int m0 = blockIdx.y * 128;
    const int n0 = blockIdx.x * 128;
    const int wm = (wid >> 2) * 64;
    const int wn = (wid & 3) * 32;

    // K-split offset
    const int kbase = blockIdx.z * K;
    A += kbase;
    B += kbase;

    const int lrow8 = ((lane >> 3) & 1) * 8 + (lane & 7);
    const int lcol8 = (lane >> 4) * 8;
    const uint32_t aBase = (uint32_t)__cvta_generic_to_shared(&As[0][wm + lrow8][lcol8]);
    const uint32_t bBase = (uint32_t)__cvta_generic_to_shared(&Bs[0][wn + lrow8][lcol8]);
    const uint32_t STG_STRIDE = 128 * LDH * 2;
    const uint32_t ROW16 = 16 * LDH * 2;

    float acc[4][4][4];
#pragma unroll
    for (int i = 0; i < 4; i++)
#pragma unroll
        for (int j = 0; j < 4; j++)
#pragma unroll
            for (int r = 0; r < 4; r++) acc[i][j][r] = 0.f;

    auto load_tiles = [&](int s, int k0) {
#pragma unroll
        for (int h = 0; h < 2; h++) {
            int idx = tid + h * 256;          // 0..511
            int row = idx >> 2;
            int ch  = idx & 3;                // 16B chunk = 8 halves
            uint32_t da = (uint32_t)__cvta_generic_to_shared(&As[s][row][ch * 8]);
            cp_async16(da, A + (size_t)(m0 + row) * lda + k0 + ch * 8);
            uint32_t db = (uint32_t)__cvta_generic_to_shared(&Bs[s][row][ch * 8]);
            int brow = n0 + row;
            const __half* src = B + (size_t)(brow < N ? brow : 0) * ldb + k0 + ch * 8;
            cp_async16_zfill(db, src, brow < N);
        }
    };

    const int nk = K / BKH;
    load_tiles(0, 0);
    asm volatile("cp.async.commit_group;\n" ::: "memory");
    if (nk > 1) load_tiles(1, BKH);
    asm volatile("cp.async.commit_group;\n" ::: "memory");

    for (int t = 0; t < nk; t++) {
        const int s = t % 3;
        asm volatile("cp.async.wait_group 1;\n" ::: "memory");
        __syncthreads();
        if (t + 2 < nk) load_tiles((t + 2) % 3, (t + 2) * BKH);
        asm volatile("cp.async.commit_group;\n" ::: "memory");

        const uint32_t aS = aBase + s * STG_STRIDE;
        const uint32_t bS = bBase + s * STG_STRIDE;
#pragma unroll
        for (int ks = 0; ks < 2; ks++) {
            const uint32_t kkb = ks * 32;     // 16 halves = 32 bytes
            uint32_t af[4][4];
#pragma unroll
            for (int mi = 0; mi < 4; mi++)
                ldsm_x4(af[mi][0], af[mi][1], af[mi][2], af[mi][3],
                        aS + mi * ROW16 + kkb);
            uint32_t bf[4][2];
#pragma unroll
            for (int n2 = 0; n2 < 2; n2++) {
                uint32_t b0, b1, b2, b3;
                ldsm_x4(b0, b1, b2, b3, bS + n2 * ROW16 + kkb);
                bf[2 * n2][0] = b0; bf[2 * n2 + 1][0] = b1;
                bf[2 * n2][1] = b2; bf[2 * n2 + 1][1] = b3;
            }
#pragma unroll
            for (int mi = 0; mi < 4; mi++)
#pragma unroll
                for (int ni = 0; ni < 4; ni++) {
                    asm volatile(
                        "mma.sync.aligned.m16n8k16.row.col.f32.f16.f16.f32 "
                        "{%0,%1,%2,%3}, {%4,%5,%6,%7}, {%8,%9}, {%0,%1,%2,%3};"
                        : "+f"(acc[mi][ni][0]), "+f"(acc[mi][ni][1]),
                          "+f"(acc[mi][ni][2]), "+f"(acc[mi][ni][3])
                        : "r"(af[mi][0]), "r"(af[mi][1]), "r"(af[mi][2]), "r"(af[mi][3]),
                          "r"(bf[ni][0]), "r"(bf[ni][1]));
                }
        }
    }

    if (EPI == 4) C += (size_t)blockIdx.z * M * ldc;

    // epilogue: acc[..][0,1] -> row r, cols c0,c0+1 ; acc[..][2,3] -> row r+8
#pragma unroll
    for (int mi = 0; mi < 4; mi++) {
        int r0 = m0 + wm + mi * 16 + g;
#pragma unroll
        for (int ni = 0; ni < 4; ni++) {
            int c0 = n0 + wn + ni * 8 + 2 * tg;
            if (c0 >= N) continue;
#pragma unroll
            for (int hh = 0; hh < 2; hh++) {
                int row = r0 + hh * 8;
                float v0 = acc[mi][ni][hh * 2 + 0];
                float v1 = acc[mi][ni][hh * 2 + 1];
                if (EPI == 1) {
                    v0 += bias[c0];     v1 += bias[c0 + 1];
                    v0 = (v0 > 20.f) ? v0 : log1pf(__expf(v0));
                    v1 = (v1 > 20.f) ? v1 : log1pf(__expf(v1));
                }
                if (EPI == 3) {
                    *(__half2*)(Ch + (size_t)row * ldc + c0) = __floats2half2_rn(v0, v1);
                } else {
                    *(float2*)(C + (size_t)row * ldc + c0) = make_float2(v0, v1);
                }
            }
        }
    }
}

// ---------------------------------------------------------------------------
// x_proj split-K reduce: xdbl = sum of 4 partials; dtin_h = fp16 of cols<128
// ---------------------------------------------------------------------------
__global__ __launch_bounds__(256) void xproj_reduce(
    const float* __restrict__ part, float* __restrict__ xdbl,
    __half* __restrict__ dtin)
{
    int i = blockIdx.x * blockDim.x + threadIdx.x;   // float4 index
    if (i >= XPN / 4) return;
    const float4* p = (const float4*)part;
    float4 v = p[i];
    float4 a = p[i + XPN / 4];
    float4 b = p[i + 2 * (XPN / 4)];
    float4 c = p[i + 3 * (XPN / 4)];
    v.x += a.x + b.x + c.x;  // (a+b)+(c+v) order fixed by compiler, deterministic
    v.y += a.y + b.y + c.y;
    v.z += a.z + b.z + c.z;
    v.w += a.w + b.w + c.w;
    ((float4*)xdbl)[i] = v;
    int col4 = (i % (XPROJ_N / 4)) * 4;
    if (col4 < DTRANK) {
        int row = i / (XPROJ_N / 4);
        __half2 h[2] = { __floats2half2_rn(v.x, v.y), __floats2half2_rn(v.z, v.w) };
        *(uint2*)(dtin + (size_t)row * DTRANK + col4) = *(uint2*)h;
    }
}

// ---------------------------------------------------------------------------
// fused fp32 -> fp16 conversion of x + 4 weight matrices (one launch)
// ---------------------------------------------------------------------------
#define NG_X  (ROWS * DMODEL / 8)
#define NG_W1 (2 * DINNER * DMODEL / 8)
#define NG_W2 (XPROJ_N * DINNER / 8)
#define NG_W3 (DINNER * DTRANK / 8)
#define NG_W4 (DMODEL * DINNER / 8)
#define NG_TOT (NG_X + NG_W1 + NG_W2 + NG_W3 + NG_W4)

__device__ __forceinline__ void cvt8(const float* in, __half* out, int i) {
    const float4* p = (const float4*)in + (size_t)i * 2;
    float4 a = p[0], b = p[1];
    __half2 h[4];
    h[0] = __floats2half2_rn(a.x, a.y);
    h[1] = __floats2half2_rn(a.z, a.w);
    h[2] = __floats2half2_rn(b.x, b.y);
    h[3] = __floats2half2_rn(b.z, b.w);
    ((uint4*)out)[i] = *(uint4*)h;
}

__global__ __launch_bounds__(256) void cvt_all_kernel(
    const float* __restrict__ x,  __half* __restrict__ xh,
    const float* __restrict__ w1, __half* __restrict__ w1h,
    const float* __restrict__ w2, __half* __restrict__ w2h,
    const float* __restrict__ w3, __half* __restrict__ w3h,
    const float* __restrict__ w4, __half* __restrict__ w4h)
{
    int i = blockIdx.x * blockDim.x + threadIdx.x;
    if (i < NG_X)                           { cvt8(x, xh, i); return; }
    i -= NG_X;
    if (i < NG_W1)                          { cvt8(w1, w1h, i); return; }
    i -= NG_W1;
    if (i < NG_W2)                          { cvt8(w2, w2h, i); return; }
    i -= NG_W2;
    if (i < NG_W3)                          { cvt8(w3, w3h, i); return; }
    i -= NG_W3;
    if (i < NG_W4)                          { cvt8(w4, w4h, i); }
}

// ---------------------------------------------------------------------------
// Causal depthwise conv1d (d_conv=4) + bias + SiLU -> u (fp32) and u_h (fp16)
// ---------------------------------------------------------------------------
__global__ __launch_bounds__(256) void conv_silu_kernel(
    const __half* __restrict__ xzh, const float* __restrict__ w,
    const float* __restrict__ bias, float* __restrict__ u,
    __half* __restrict__ uh)
{
    int idx = blockIdx.x * blockDim.x + threadIdx.x;
    if (idx >= ROWS * DINNER) return;
    int d = idx & (DINNER - 1);
    int row = idx >> 11;
    int l = row & (LSEQ - 1);

    float w0 = w[d * 4 + 0], w1 = w[d * 4 + 1], w2 = w[d * 4 + 2], w3 = w[d * 4 + 3];
    const __half* base = xzh + (size_t)row * (2 * DINNER) + d;
    float acc = bias[d] + w3 * __half2float(base[0]);
    if (l >= 1) acc = fmaf(w2, __half2float(base[-(2 * DINNER)]), acc);
    if (l >= 2) acc = fmaf(w1, __half2float(base[-2 * (2 * DINNER)]), acc);
    if (l >= 3) acc = fmaf(w0, __half2float(base[-3 * (2 * DINNER)]), acc);
    float sact = acc / (1.f + __expf(-acc));
    u[idx] = sact;
    uh[idx] = __float2half(sact);
}

// ---------------------------------------------------------------------------
// Chunked selective scan (exact chunk decomposition via exp(A * sum dt)).
// ---------------------------------------------------------------------------
__device__ __forceinline__ void load_bc16(const float* __restrict__ p, float* v) {
    float4 a = ((const float4*)p)[0], b2 = ((const float4*)p)[1];
    float4 c = ((const float4*)p)[2], e = ((const float4*)p)[3];
    v[0]=a.x; v[1]=a.y; v[2]=a.z; v[3]=a.w;
    v[4]=b2.x; v[5]=b2.y; v[6]=b2.z; v[7]=b2.w;
    v[8]=c.x; v[9]=c.y; v[10]=c.z; v[11]=c.w;
    v[12]=e.x; v[13]=e.y; v[14]=e.z; v[15]=e.w;
}

__global__ __launch_bounds__(128) void scan_pass1(
    const float* __restrict__ u, const float* __restrict__ dt,
    const float* __restrict__ xdbl, const float* __restrict__ A_log,
    float* __restrict__ hpart, float* __restrict__ Ssum)
{
    const int d = blockIdx.x * 128 + threadIdx.x;
    const int c = blockIdx.y;
    const int b = blockIdx.z;

    float A[DSTATE];
    const float a0 = -__expf(A_log[d * DSTATE]);
    bool structured = true;
#pragma unroll
    for (int n = 0; n < DSTATE; n++) {
        A[n] = -__expf(A_log[d * DSTATE + n]);
        structured = structured &&
            (fabsf(A[n] - (float)(n + 1) * a0) <= 1e-4f * (float)(n + 1));
    }

    float h[DSTATE];
#pragma unroll
    for (int n = 0; n < DSTATE; n++) h[n] = 0.f;
    float S = 0.f;

    const int l0 = c * CLEN;
    if (structured) {
        for (int l = l0; l < l0 + CLEN; l++) {
            const size_t row = (size_t)b * LSEQ + l;
            const float ut  = u[row * DINNER + d];
            const float dtt = dt[row * DINNER + d];
            float Bv[16];
            load_bc16(xdbl + row * XPROJ_N + DTRANK, Bv);
            S += dtt;
            const float dtu = dtt * ut;
            const float E = __expf(dtt * a0);
            float dA = E;
#pragma unroll
            for (int n = 0; n < DSTATE; n++) {
                h[n] = fmaf(dA, h[n], dtu * Bv[n]);
                dA *= E;
            }
        }
    } else {
        for (int l = l0; l < l0 + CLEN; l++) {
            const size_t row = (size_t)b * LSEQ + l;
            const float ut  = u[row * DINNER + d];
            const float dtt = dt[row * DINNER + d];
            float Bv[16];
            load_bc16(xdbl + row * XPROJ_N + DTRANK, Bv);
            S += dtt;
            const float dtu = dtt * ut;
#pragma unroll
            for (int n = 0; n < DSTATE; n++)
                h[n] = fmaf(__expf(dtt * A[n]), h[n], dtu * Bv[n]);
        }
    }

    const size_t base = ((size_t)(b * CHUNKS + c) * DSTATE) * DINNER + d;
#pragma unroll
    for (int n = 0; n < DSTATE; n++) hpart[base + (size_t)n * DINNER] = h[n];
    Ssum[(size_t)(b * CHUNKS + c) * DINNER + d] = S;
}

__global__ __launch_bounds__(128) void scan_combine(
    const float* __restrict__ A_log, const float* __restrict__ Ssum,
    const float* __restrict__ hpart, float* __restrict__ hstart)
{
    const int d = blockIdx.x * 128 + threadIdx.x;
    const int n = blockIdx.y;
    const int b = blockIdx.z;
    const float An = -__expf(A_log[d * DSTATE + n]);
    float h = 0.f;
    for (int c = 0; c < CHUNKS; c++) {
        const size_t idx = ((size_t)(b * CHUNKS + c) * DSTATE + n) * DINNER + d;
        hstart[idx] = h;
        const float P = __expf(An * Ssum[(size_t)(b * CHUNKS + c) * DINNER + d]);
        h = fmaf(P, h, hpart[idx]);
    }
}

__global__ __launch_bounds__(128) void scan_pass2(
    const float* __restrict__ u, const float* __restrict__ dt,
    const float* __restrict__ xdbl, const __half* __restrict__ xzh,
    const float* __restrict__ A_log, const float* __restrict__ Dp,
    const float* __restrict__ hstart, __half* __restrict__ yh)
{
    const int d = blockIdx.x * 128 + threadIdx.x;
    const int c = blockIdx.y;
    const int b = blockIdx.z;

    float A[DSTATE];
    const float a0 = -__expf(A_log[d * DSTATE]);
    bool structured = true;
#pragma unroll
    for (int n = 0; n < DSTATE; n++) {
        A[n] = -__expf(A_log[d * DSTATE + n]);
        structured = structured &&
            (fabsf(A[n] - (float)(n + 1) * a0) <= 1e-4f * (float)(n + 1));
    }
    const float Dd = Dp[d];

    float h[DSTATE];
    const size_t hbase = ((size_t)(b * CHUNKS + c) * DSTATE) * DINNER + d;
#pragma unroll
    for (int n = 0; n < DSTATE; n++) h[n] = hstart[hbase + (size_t)n * DINNER];

    const int l0 = c * CLEN;
    if (structured) {
        for (int l = l0; l < l0 + CLEN; l++) {
            const size_t row = (size_t)b * LSEQ + l;
            const float ut  = u[row * DINNER + d];
            const float dtt = dt[row * DINNER + d];
            const float zt  = __half2float(xzh[row * (2 * DINNER) + DINNER + d]);
            float Bv[16], Cv[16];
            load_bc16(xdbl + row * XPROJ_N + DTRANK, Bv);
            load_bc16(xdbl + row * XPROJ_N + DTRANK + DSTATE, Cv);
            const float dtu = dtt * ut;
            const float E = __expf(dtt * a0);
            float dA = E;
            float acc = 0.f;
#pragma unroll
            for (int n = 0; n < DSTATE; n++) {
                h[n] = fmaf(dA, h[n], dtu * Bv[n]);
                acc = fmaf(h[n], Cv[n], acc);
                dA *= E;
            }
            float yv = fmaf(ut, Dd, acc);
            float sz = zt / (1.f + __expf(-zt));
            yh[row * DINNER + d] = __float2half(yv * sz);
        }
    } else {
        for (int l = l0; l < l0 + CLEN; l++) {
            const size_t row = (size_t)b * LSEQ + l;
            const float ut  = u[row * DINNER + d];
            const float dtt = dt[row * DINNER + d];
            const float zt  = __half2float(xzh[row * (2 * DINNER) + DINNER + d]);
            float Bv[16], Cv[16];
            load_bc16(xdbl + row * XPROJ_N + DTRANK, Bv);
            load_bc16(xdbl + row * XPROJ_N + DTRANK + DSTATE, Cv);
            const float dtu = dtt * ut;
            float acc = 0.f;
#pragma unroll
            for (int n = 0; n < DSTATE; n++) {
                h[n] = fmaf(__expf(dtt * A[n]), h[n], dtu * Bv[n]);
                acc = fmaf(h[n], Cv[n], acc);
            }
            float yv = fmaf(ut, Dd, acc);
            float sz = zt / (1.f + __expf(-zt));
            yh[row * DINNER + d] = __float2half(yv * sz);
        }
    }
}

// ---------------------------------------------------------------------------
extern "C" void kernel_launch(void* const* d_in, const int* in_sizes, int n_in,
                              void* d_out, int out_size)
{
    const float* x          = (const float*)d_in[0];
    const float* in_proj_w  = (const float*)d_in[1];
    const float* conv_w     = (const float*)d_in[2];
    const float* conv_b     = (const float*)d_in[3];
    const float* x_proj_w   = (const float*)d_in[4];
    const float* dt_proj_w  = (const float*)d_in[5];
    const float* dt_proj_b  = (const float*)d_in[6];
    const float* A_log      = (const float*)d_in[7];
    const float* Dp         = (const float*)d_in[8];
    const float* out_proj_w = (const float*)d_in[9];
    float* out = (float*)d_out;

    float *u, *xdbl, *xp4, *dtb, *hp, *hs, *Ss;
    __half *xzh, *uh, *dtin_h, *yh, *xh, *w1h, *w2h, *w3h, *w4h;
    cudaGetSymbolAddress((void**)&xzh,    g_xzh);
    cudaGetSymbolAddress((void**)&u,      g_u);
    cudaGetSymbolAddress((void**)&uh,     g_uh);
    cudaGetSymbolAddress((void**)&xdbl,   g_xdbl);
    cudaGetSymbolAddress((void**)&xp4,    g_xp4);
    cudaGetSymbolAddress((void**)&dtin_h, g_dtin_h);
    cudaGetSymbolAddress((void**)&dtb,    g_dt);
    cudaGetSymbolAddress((void**)&yh,     g_yh);
    cudaGetSymbolAddress((void**)&xh,     g_xh);
    cudaGetSymbolAddress((void**)&w1h,    g_w1h);
    cudaGetSymbolAddress((void**)&w2h,    g_w2h);
    cudaGetSymbolAddress((void**)&w3h,    g_w3h);
    cudaGetSymbolAddress((void**)&w4h,    g_w4h);
    cudaGetSymbolAddress((void**)&hp,     g_hpart);
    cudaGetSymbolAddress((void**)&hs,     g_hstart);
    cudaGetSymbolAddress((void**)&Ss,     g_S);

    cudaFuncSetAttribute(hgemm_nt<0>, cudaFuncAttributeMaxDynamicSharedMemorySize, HSMEM_BYTES);
    cudaFuncSetAttribute(hgemm_nt<1>, cudaFuncAttributeMaxDynamicSharedMemorySize, HSMEM_BYTES);
    cudaFuncSetAttribute(hgemm_nt<3>, cudaFuncAttributeMaxDynamicSharedMemorySize, HSMEM_BYTES);
    cudaFuncSetAttribute(hgemm_nt<4>, cudaFuncAttributeMaxDynamicSharedMemorySize, HSMEM_BYTES);

    // 0) fused fp16 conversion of x + all weights (one launch)
    cvt_all_kernel<<<(NG_TOT + 255) / 256, 256>>>(x, xh, in_proj_w, w1h,
                                                  x_proj_w, w2h, dt_proj_w, w3h,
                                                  out_proj_w, w4h);

    // 1) xz = x @ in_proj_w^T -> fp16 [4096, 4096]
    hgemm_nt<3><<<dim3(32, 32), 256, HSMEM_BYTES>>>(xh, w1h, nullptr, nullptr, xzh,
                                       ROWS, 2 * DINNER, DMODEL,
                                       DMODEL, DMODEL, 2 * DINNER);
    // 2) u = silu(causal_conv(xb) + b)   [4096, 2048]  (fp32 + fp16)
    conv_silu_kernel<<<(ROWS * DINNER) / 256, 256>>>(xzh, conv_w, conv_b, u, uh);
    // 3) x_dbl = u @ x_proj_w^T          [4096, 160]  split-K x4 + reduce
    hgemm_nt<4><<<dim3(2, 32, KSPLIT), 256, HSMEM_BYTES>>>(uh, w2h, xp4, nullptr, nullptr,
                                       ROWS, XPROJ_N, DINNER / KSPLIT,
                                       DINNER, DINNER, XPROJ_N);
    xproj_reduce<<<(XPN / 4 + 255) / 256, 256>>>(xp4, xdbl, dtin_h);
    // 4) dt = softplus(dt_in @ dt_proj_w^T + b)   [4096, 2048]
    hgemm_nt<1><<<dim3(16, 32), 256, HSMEM_BYTES>>>(dtin_h, w3h, dtb, dt_proj_b, nullptr,
                                       ROWS, DINNER, DTRANK,
                                       DTRANK, DTRANK, DINNER);
    // 5) chunked selective scan -> y (fp16)
    scan_pass1<<<dim3(DINNER / 128, CHUNKS, BATCH), 128>>>(u, dtb, xdbl, A_log, hp, Ss);
    scan_combine<<<dim3(DINNER / 128, DSTATE, BATCH), 128>>>(A_log, Ss, hp, hs);
    scan_pass2<<<dim3(DINNER / 128, CHUNKS, BATCH), 128>>>(u, dtb, xdbl, xzh, A_log, Dp, hs, yh);
    // 6) out = y @ out_proj_w^T          [4096, 1024]
    hgemm_nt<0><<<dim3(8, 32), 256, HSMEM_BYTES>>>(yh, w4h, out, nullptr, nullptr,
                                      ROWS, DMODEL, DINNER,
                                      DINNER, DINNER, DMODEL);
}

// round 9
// speedup vs baseline: 9.4051x; 1.0297x over previous
#include <cuda_runtime.h>
#include <cuda_fp16.h>
#include <math.h>
#include <stdint.h>

// Problem constants
#define BATCH 2
#define LSEQ 2048
#define DMODEL 1024
#define DINNER 2048
#define DSTATE 16
#define DTRANK 128
#define ROWS (BATCH * LSEQ)           // 4096
#define XPROJ_N (DTRANK + 2 * DSTATE) // 160
#define CHUNKS 32
#define CLEN (LSEQ / CHUNKS)          // 64
#define KSPLIT 4
#define XPN (ROWS * XPROJ_N)          // 655360

// Scratch (device globals: allocation-free rule)
__device__ __half g_xzh[(size_t)ROWS * (2 * DINNER)];  // in_proj out (xb | z), fp16
__device__ __half g_uh[(size_t)ROWS * DINNER];
__device__ float  g_xdbl[(size_t)ROWS * XPROJ_N];
__device__ float  g_xp4[(size_t)KSPLIT * XPN];         // x_proj split-K partials
__device__ __half g_dtin_h[(size_t)ROWS * DTRANK];
__device__ float  g_dt[(size_t)ROWS * DINNER];
__device__ __half g_yh[(size_t)ROWS * DINNER];
__device__ __half g_xh[(size_t)ROWS * DMODEL];
__device__ __half g_w1h[(size_t)(2 * DINNER) * DMODEL];
__device__ __half g_w2h[(size_t)XPROJ_N * DINNER];
__device__ __half g_w3h[(size_t)DINNER * DTRANK];
__device__ __half g_w4h[(size_t)DMODEL * DINNER];
__device__ float  g_hpart[(size_t)BATCH * CHUNKS * DSTATE * DINNER];
__device__ float  g_hstart[(size_t)BATCH * CHUNKS * DSTATE * DINNER];
__device__ float  g_S[(size_t)BATCH * CHUNKS * DINNER];

// ---------------------------------------------------------------------------
// helpers
// ---------------------------------------------------------------------------
__device__ __forceinline__ void cp_async16(uint32_t saddr, const void* g) {
    asm volatile("cp.async.cg.shared.global [%0], [%1], 16;\n" :: "r"(saddr), "l"(g));
}
__device__ __forceinline__ void cp_async16_zfill(uint32_t saddr, const void* g, bool pred) {
    int sz = pred ? 16 : 0;
    asm volatile("cp.async.cg.shared.global [%0], [%1], 16, %2;\n" :: "r"(saddr), "l"(g), "r"(sz));
}
__device__ __forceinline__ void ldsm_x4(uint32_t& r0, uint32_t& r1, uint32_t& r2,
                                        uint32_t& r3, uint32_t addr) {
    asm volatile("ldmatrix.sync.aligned.m8n8.x4.shared.b16 {%0,%1,%2,%3}, [%4];"
                 : "=r"(r0), "=r"(r1), "=r"(r2), "=r"(r3) : "r"(addr));
}

// ---------------------------------------------------------------------------
// fp16 tensor-core GEMM: C[M,N] = epi( A[M,K](lda) @ B[N,K](ldb)^T )
// BM=BN=128, BK=32 halves, 256 threads (2x4 warps, warp tile 64x32).
// 4-stage cp.async pipeline (wait_group 2), ldmatrix fragment loads.
// blockIdx.z selects a K-split slice (A/B advanced by z*K; K = per-slice span).
// EPI: 0 fp32 C; 1 softplus(acc+bias) fp32; 3 fp16 Ch only;
//      4 split-K fp32 partial to C + z*M*ldc.
// ---------------------------------------------------------------------------
#define BKH 32
#define PADH 8
#define LDH (BKH + PADH)   // 40 halves/row; 80B stride -> conflict-free ldmatrix
#define NSTG 4
#define HSMEM_BYTES (2 * NSTG * 128 * LDH * 2)   // 4 stages x (A+B) = 81920 B

template <int EPI>
__global__ __launch_bounds__(256, 2) void hgemm_nt(
    const __half* __restrict__ A, const __half* __restrict__ B,
    float* __restrict__ C, const float* __restrict__ bias,
    __half* __restrict__ Ch,
    int M, int N, int K, int lda, int ldb, int ldc)
{
    extern __shared__ __half sh[];
    __half (*As)[128][LDH] = (__half(*)[128][LDH])sh;
    __half (*Bs)[128][LDH] = (__half(*)[128][LDH])(sh + NSTG * 128 * LDH);

    const int tid  = threadIdx.x;
    const int wid  = tid >> 5;
    const int lane = tid & 31;
    const int g    = lane >> 2;
    const int tg   = lane & 3;
    const int m0 = blockIdx.y * 128;
    const int n0 = blockIdx.x * 128;
    const int wm = (wid >> 2) * 64;
    const int wn = (wid & 3) * 32;

    // K-split offset
    const int kbase = blockIdx.z * K;
    A += kbase;
    B += kbase;

    const int lrow8 = ((lane >> 3) & 1) * 8 + (lane & 7);
    const int lcol8 = (lane >> 4) * 8;
    const uint32_t aBase = (uint32_t)__cvta_generic_to_shared(&As[0][wm + lrow8][lcol8]);
    const uint32_t bBase = (uint32_t)__cvta_generic_to_shared(&Bs[0][wn + lrow8][lcol8]);
    const uint32_t STG_STRIDE = 128 * LDH * 2;
    const uint32_t ROW16 = 16 * LDH * 2;

    float acc[4][4][4];
#pragma unroll
    for (int i = 0; i < 4; i++)
#pragma unroll
        for (int j = 0; j < 4; j++)
#pragma unroll
            for (int r = 0; r < 4; r++) acc[i][j][r] = 0.f;

    auto load_tiles = [&](int s, int k0) {
#pragma unroll
        for (int h = 0; h < 2; h++) {
            int idx = tid + h * 256;          // 0..511
            int row = idx >> 2;
            int ch  = idx & 3;                // 16B chunk = 8 halves
            uint32_t da = (uint32_t)__cvta_generic_to_shared(&As[s][row][ch * 8]);
            cp_async16(da, A + (size_t)(m0 + row) * lda + k0 + ch * 8);
            uint32_t db = (uint32_t)__cvta_generic_to_shared(&Bs[s][row][ch * 8]);
            int brow = n0 + row;
            const __half* src = B + (size_t)(brow < N ? brow : 0) * ldb + k0 + ch * 8;
            cp_async16_zfill(db, src, brow < N);
        }
    };

    const int nk = K / BKH;
#pragma unroll
    for (int t = 0; t < NSTG - 1; t++) {
        if (t < nk) load_tiles(t, t * BKH);
        asm volatile("cp.async.commit_group;\n" ::: "memory");
    }

    for (int t = 0; t < nk; t++) {
        const int s = t % NSTG;
        asm volatile("cp.async.wait_group %0;\n" :: "n"(NSTG - 2) : "memory");
        __syncthreads();
        if (t + NSTG - 1 < nk) load_tiles((t + NSTG - 1) % NSTG, (t + NSTG - 1) * BKH);
        asm volatile("cp.async.commit_group;\n" ::: "memory");

        const uint32_t aS = aBase + s * STG_STRIDE;
        const uint32_t bS = bBase + s * STG_STRIDE;
#pragma unroll
        for (int ks = 0; ks < 2; ks++) {
            const uint32_t kkb = ks * 32;     // 16 halves = 32 bytes
            uint32_t af[4][4];
#pragma unroll
            for (int mi = 0; mi < 4; mi++)
                ldsm_x4(af[mi][0], af[mi][1], af[mi][2], af[mi][3],
                        aS + mi * ROW16 + kkb);
            uint32_t bf[4][2];
#pragma unroll
            for (int n2 = 0; n2 < 2; n2++) {
                uint32_t b0, b1, b2, b3;
                ldsm_x4(b0, b1, b2, b3, bS + n2 * ROW16 + kkb);
                bf[2 * n2][0] = b0; bf[2 * n2 + 1][0] = b1;
                bf[2 * n2][1] = b2; bf[2 * n2 + 1][1] = b3;
            }
#pragma unroll
            for (int mi = 0; mi < 4; mi++)
#pragma unroll
                for (int ni = 0; ni < 4; ni++) {
                    asm volatile(
                        "mma.sync.aligned.m16n8k16.row.col.f32.f16.f16.f32 "
                        "{%0,%1,%2,%3}, {%4,%5,%6,%7}, {%8,%9}, {%0,%1,%2,%3};"
                        : "+f"(acc[mi][ni][0]), "+f"(acc[mi][ni][1]),
                          "+f"(acc[mi][ni][2]), "+f"(acc[mi][ni][3])
                        : "r"(af[mi][0]), "r"(af[mi][1]), "r"(af[mi][2]), "r"(af[mi][3]),
                          "r"(bf[ni][0]), "r"(bf[ni][1]));
                }
        }
    }

    if (EPI == 4) C += (size_t)blockIdx.z * M * ldc;

    // epilogue: acc[..][0,1] -> row r, cols c0,c0+1 ; acc[..][2,3] -> row r+8
#pragma unroll
    for (int mi = 0; mi < 4; mi++) {
        int r0 = m0 + wm + mi * 16 + g;
#pragma unroll
        for (int ni = 0; ni < 4; ni++) {
            int c0 = n0 + wn + ni * 8 + 2 * tg;
            if (c0 >= N) continue;
#pragma unroll
            for (int hh = 0; hh < 2; hh++) {
                int row = r0 + hh * 8;
                float v0 = acc[mi][ni][hh * 2 + 0];
                float v1 = acc[mi][ni][hh * 2 + 1];
                if (EPI == 1) {
                    v0 += bias[c0];     v1 += bias[c0 + 1];
                    v0 = (v0 > 20.f) ? v0 : log1pf(__expf(v0));
                    v1 = (v1 > 20.f) ? v1 : log1pf(__expf(v1));
                }
                if (EPI == 3) {
                    *(__half2*)(Ch + (size_t)row * ldc + c0) = __floats2half2_rn(v0, v1);
                } else {
                    *(float2*)(C + (size_t)row * ldc + c0) = make_float2(v0, v1);
                }
            }
        }
    }
}

// ---------------------------------------------------------------------------
// x_proj split-K reduce: xdbl = sum of 4 partials; dtin_h = fp16 of cols<128
// ---------------------------------------------------------------------------
__global__ __launch_bounds__(256) void xproj_reduce(
    const float* __restrict__ part, float* __restrict__ xdbl,
    __half* __restrict__ dtin)
{
    int i = blockIdx.x * blockDim.x + threadIdx.x;   // float4 index
    if (i >= XPN / 4) return;
    const float4* p = (const float4*)part;
    float4 v = p[i];
    float4 a = p[i + XPN / 4];
    float4 b = p[i + 2 * (XPN / 4)];
    float4 c = p[i + 3 * (XPN / 4)];
    v.x += a.x + b.x + c.x;
    v.y += a.y + b.y + c.y;
    v.z += a.z + b.z + c.z;
    v.w += a.w + b.w + c.w;
    ((float4*)xdbl)[i] = v;
    int col4 = (i % (XPROJ_N / 4)) * 4;
    if (col4 < DTRANK) {
        int row = i / (XPROJ_N / 4);
        __half2 h[2] = { __floats2half2_rn(v.x, v.y), __floats2half2_rn(v.z, v.w) };
        *(uint2*)(dtin + (size_t)row * DTRANK + col4) = *(uint2*)h;
    }
}

// ---------------------------------------------------------------------------
// fused fp32 -> fp16 conversion of x + 4 weight matrices (one launch)
// ---------------------------------------------------------------------------
#define NG_X  (ROWS * DMODEL / 8)
#define NG_W1 (2 * DINNER * DMODEL / 8)
#define NG_W2 (XPROJ_N * DINNER / 8)
#define NG_W3 (DINNER * DTRANK / 8)
#define NG_W4 (DMODEL * DINNER / 8)
#define NG_TOT (NG_X + NG_W1 + NG_W2 + NG_W3 + NG_W4)

__device__ __forceinline__ void cvt8(const float* in, __half* out, int i) {
    const float4* p = (const float4*)in + (size_t)i * 2;
    float4 a = p[0], b = p[1];
    __half2 h[4];
    h[0] = __floats2half2_rn(a.x, a.y);
    h[1] = __floats2half2_rn(a.z, a.w);
    h[2] = __floats2half2_rn(b.x, b.y);
    h[3] = __floats2half2_rn(b.z, b.w);
    ((uint4*)out)[i] = *(uint4*)h;
}

__global__ __launch_bounds__(256) void cvt_all_kernel(
    const float* __restrict__ x,  __half* __restrict__ xh,
    const float* __restrict__ w1, __half* __restrict__ w1h,
    const float* __restrict__ w2, __half* __restrict__ w2h,
    const float* __restrict__ w3, __half* __restrict__ w3h,
    const float* __restrict__ w4, __half* __restrict__ w4h)
{
    int i = blockIdx.x * blockDim.x + threadIdx.x;
    if (i < NG_X)                           { cvt8(x, xh, i); return; }
    i -= NG_X;
    if (i < NG_W1)                          { cvt8(w1, w1h, i); return; }
    i -= NG_W1;
    if (i < NG_W2)                          { cvt8(w2, w2h, i); return; }
    i -= NG_W2;
    if (i < NG_W3)                          { cvt8(w3, w3h, i); return; }
    i -= NG_W3;
    if (i < NG_W4)                          { cvt8(w4, w4h, i); }
}

// ---------------------------------------------------------------------------
// Causal depthwise conv1d (d_conv=4) + bias + SiLU -> u_h (fp16 only)
// ---------------------------------------------------------------------------
__global__ __launch_bounds__(256) void conv_silu_kernel(
    const __half* __restrict__ xzh, const float* __restrict__ w,
    const float* __restrict__ bias, __half* __restrict__ uh)
{
    int idx = blockIdx.x * blockDim.x + threadIdx.x;
    if (idx >= ROWS * DINNER) return;
    int d = idx & (DINNER - 1);
    int row = idx >> 11;
    int l = row & (LSEQ - 1);

    float w0 = w[d * 4 + 0], w1 = w[d * 4 + 1], w2 = w[d * 4 + 2], w3 = w[d * 4 + 3];
    const __half* base = xzh + (size_t)row * (2 * DINNER) + d;
    float acc = bias[d] + w3 * __half2float(base[0]);
    if (l >= 1) acc = fmaf(w2, __half2float(base[-(2 * DINNER)]), acc);
    if (l >= 2) acc = fmaf(w1, __half2float(base[-2 * (2 * DINNER)]), acc);
    if (l >= 3) acc = fmaf(w0, __half2float(base[-3 * (2 * DINNER)]), acc);
    float sact = acc / (1.f + __expf(-acc));
    uh[idx] = __float2half(sact);
}

// ---------------------------------------------------------------------------
// Chunked selective scan (exact chunk decomposition via exp(A * sum dt)).
// ---------------------------------------------------------------------------
__device__ __forceinline__ void load_bc16(const float* __restrict__ p, float* v) {
    float4 a = ((const float4*)p)[0], b2 = ((const float4*)p)[1];
    float4 c = ((const float4*)p)[2], e = ((const float4*)p)[3];
    v[0]=a.x; v[1]=a.y; v[2]=a.z; v[3]=a.w;
    v[4]=b2.x; v[5]=b2.y; v[6]=b2.z; v[7]=b2.w;
    v[8]=c.x; v[9]=c.y; v[10]=c.z; v[11]=c.w;
    v[12]=e.x; v[13]=e.y; v[14]=e.z; v[15]=e.w;
}

__global__ __launch_bounds__(128) void scan_pass1(
    const __half* __restrict__ uh, const float* __restrict__ dt,
    const float* __restrict__ xdbl, const float* __restrict__ A_log,
    float* __restrict__ hpart, float* __restrict__ Ssum)
{
    const int d = blockIdx.x * 128 + threadIdx.x;
    const int c = blockIdx.y;
    const int b = blockIdx.z;

    float A[DSTATE];
    const float a0 = -__expf(A_log[d * DSTATE]);
    bool structured = true;
#pragma unroll
    for (int n = 0; n < DSTATE; n++) {
        A[n] = -__expf(A_log[d * DSTATE + n]);
        structured = structured &&
            (fabsf(A[n] - (float)(n + 1) * a0) <= 1e-4f * (float)(n + 1));
    }

    float h[DSTATE];
#pragma unroll
    for (int n = 0; n < DSTATE; n++) h[n] = 0.f;
    float S = 0.f;

    const int l0 = c * CLEN;
    if (structured) {
        for (int l = l0; l < l0 + CLEN; l++) {
            const size_t row = (size_t)b * LSEQ + l;
            const float ut  = __half2float(uh[row * DINNER + d]);
            const float dtt = dt[row * DINNER + d];
            float Bv[16];
            load_bc16(xdbl + row * XPROJ_N + DTRANK, Bv);
            S += dtt;
            const float dtu = dtt * ut;
            const float E = __expf(dtt * a0);
            float dA = E;
#pragma unroll
            for (int n = 0; n < DSTATE; n++) {
                h[n] = fmaf(dA, h[n], dtu * Bv[n]);
                dA *= E;
            }
        }
    } else {
        for (int l = l0; l < l0 + CLEN; l++) {
            const size_t row = (size_t)b * LSEQ + l;
            const float ut  = __half2float(uh[row * DINNER + d]);
            const float dtt = dt[row * DINNER + d];
            float Bv[16];
            load_bc16(xdbl + row * XPROJ_N + DTRANK, Bv);
            S += dtt;
            const float dtu = dtt * ut;
#pragma unroll
            for (int n = 0; n < DSTATE; n++)
                h[n] = fmaf(__expf(dtt * A[n]), h[n], dtu * Bv[n]);
        }
    }

    const size_t base = ((size_t)(b * CHUNKS + c) * DSTATE) * DINNER + d;
#pragma unroll
    for (int n = 0; n < DSTATE; n++) hpart[base + (size_t)n * DINNER] = h[n];
    Ssum[(size_t)(b * CHUNKS + c) * DINNER + d] = S;
}

__global__ __launch_bounds__(128) void scan_combine(
    const float* __restrict__ A_log, const float* __restrict__ Ssum,
    const float* __restrict__ hpart, float* __restrict__ hstart)
{
    const int d = blockIdx.x * 128 + threadIdx.x;
    const int n = blockIdx.y;
    const int b = blockIdx.z;
    const float An = -__expf(A_log[d * DSTATE + n]);
    float h = 0.f;
    for (int c = 0; c < CHUNKS; c++) {
        const size_t idx = ((size_t)(b * CHUNKS + c) * DSTATE + n) * DINNER + d;
        hstart[idx] = h;
        const float P = __expf(An * Ssum[(size_t)(b * CHUNKS + c) * DINNER + d]);
        h = fmaf(P, h, hpart[idx]);
    }
}

__global__ __launch_bounds__(128) void scan_pass2(
    const __half* __restrict__ uh, const float* __restrict__ dt,
    const float* __restrict__ xdbl, const __half* __restrict__ xzh,
    const float* __restrict__ A_log, const float* __restrict__ Dp,
    const float* __restrict__ hstart, __half* __restrict__ yh)
{
    const int d = blockIdx.x * 128 + threadIdx.x;
    const int c = blockIdx.y;
    const int b = blockIdx.z;

    float A[DSTATE];
    const float a0 = -__expf(A_log[d * DSTATE]);
    bool structured = true;
#pragma unroll
    for (int n = 0; n < DSTATE; n++) {
        A[n] = -__expf(A_log[d * DSTATE + n]);
        structured = structured &&
            (fabsf(A[n] - (float)(n + 1) * a0) <= 1e-4f * (float)(n + 1));
    }
    const float Dd = Dp[d];

    float h[DSTATE];
    const size_t hbase = ((size_t)(b * CHUNKS + c) * DSTATE) * DINNER + d;
#pragma unroll
    for (int n = 0; n < DSTATE; n++) h[n] = hstart[hbase + (size_t)n * DINNER];

    const int l0 = c * CLEN;
    if (structured) {
        for (int l = l0; l < l0 + CLEN; l++) {
            const size_t row = (size_t)b * LSEQ + l;
            const float ut  = __half2float(uh[row * DINNER + d]);
            const float dtt = dt[row * DINNER + d];
            const float zt  = __half2float(xzh[row * (2 * DINNER) + DINNER + d]);
            float Bv[16], Cv[16];
            load_bc16(xdbl + row * XPROJ_N + DTRANK, Bv);
            load_bc16(xdbl + row * XPROJ_N + DTRANK + DSTATE, Cv);
            const float dtu = dtt * ut;
            const float E = __expf(dtt * a0);
            float dA = E;
            float acc = 0.f;
#pragma unroll
            for (int n = 0; n < DSTATE; n++) {
                h[n] = fmaf(dA, h[n], dtu * Bv[n]);
                acc = fmaf(h[n], Cv[n], acc);
                dA *= E;
            }
            float yv = fmaf(ut, Dd, acc);
            float sz = zt / (1.f + __expf(-zt));
            yh[row * DINNER + d] = __float2half(yv * sz);
        }
    } else {
        for (int l = l0; l < l0 + CLEN; l++) {
            const size_t row = (size_t)b * LSEQ + l;
            const float ut  = __half2float(uh[row * DINNER + d]);
            const float dtt = dt[row * DINNER + d];
            const float zt  = __half2float(xzh[row * (2 * DINNER) + DINNER + d]);
            float Bv[16], Cv[16];
            load_bc16(xdbl + row * XPROJ_N + DTRANK, Bv);
            load_bc16(xdbl + row * XPROJ_N + DTRANK + DSTATE, Cv);
            const float dtu = dtt * ut;
            float acc = 0.f;
#pragma unroll
            for (int n = 0; n < DSTATE; n++) {
                h[n] = fmaf(__expf(dtt * A[n]), h[n], dtu * Bv[n]);
                acc = fmaf(h[n], Cv[n], acc);
            }
            float yv = fmaf(ut, Dd, acc);
            float sz = zt / (1.f + __expf(-zt));
            yh[row * DINNER + d] = __float2half(yv * sz);
        }
    }
}

// ---------------------------------------------------------------------------
extern "C" void kernel_launch(void* const* d_in, const int* in_sizes, int n_in,
                              void* d_out, int out_size)
{
    const float* x          = (const float*)d_in[0];
    const float* in_proj_w  = (const float*)d_in[1];
    const float* conv_w     = (const float*)d_in[2];
    const float* conv_b     = (const float*)d_in[3];
    const float* x_proj_w   = (const float*)d_in[4];
    const float* dt_proj_w  = (const float*)d_in[5];
    const float* dt_proj_b  = (const float*)d_in[6];
    const float* A_log      = (const float*)d_in[7];
    const float* Dp         = (const float*)d_in[8];
    const float* out_proj_w = (const float*)d_in[9];
    float* out = (float*)d_out;

    float *xdbl, *xp4, *dtb, *hp, *hs, *Ss;
    __half *xzh, *uh, *dtin_h, *yh, *xh, *w1h, *w2h, *w3h, *w4h;
    cudaGetSymbolAddress((void**)&xzh,    g_xzh);
    cudaGetSymbolAddress((void**)&uh,     g_uh);
    cudaGetSymbolAddress((void**)&xdbl,   g_xdbl);
    cudaGetSymbolAddress((void**)&xp4,    g_xp4);
    cudaGetSymbolAddress((void**)&dtin_h, g_dtin_h);
    cudaGetSymbolAddress((void**)&dtb,    g_dt);
    cudaGetSymbolAddress((void**)&yh,     g_yh);
    cudaGetSymbolAddress((void**)&xh,     g_xh);
    cudaGetSymbolAddress((void**)&w1h,    g_w1h);
    cudaGetSymbolAddress((void**)&w2h,    g_w2h);
    cudaGetSymbolAddress((void**)&w3h,    g_w3h);
    cudaGetSymbolAddress((void**)&w4h,    g_w4h);
    cudaGetSymbolAddress((void**)&hp,     g_hpart);
    cudaGetSymbolAddress((void**)&hs,     g_hstart);
    cudaGetSymbolAddress((void**)&Ss,     g_S);

    cudaFuncSetAttribute(hgemm_nt<0>, cudaFuncAttributeMaxDynamicSharedMemorySize, HSMEM_BYTES);
    cudaFuncSetAttribute(hgemm_nt<1>, cudaFuncAttributeMaxDynamicSharedMemorySize, HSMEM_BYTES);
    cudaFuncSetAttribute(hgemm_nt<3>, cudaFuncAttributeMaxDynamicSharedMemorySize, HSMEM_BYTES);
    cudaFuncSetAttribute(hgemm_nt<4>, cudaFuncAttributeMaxDynamicSharedMemorySize, HSMEM_BYTES);

    // 0) fused fp16 conversion of x + all weights (one launch)
    cvt_all_kernel<<<(NG_TOT + 255) / 256, 256>>>(x, xh, in_proj_w, w1h,
                                                  x_proj_w, w2h, dt_proj_w, w3h,
                                                  out_proj_w, w4h);

    // 1) xz = x @ in_proj_w^T -> fp16 [4096, 4096]
    hgemm_nt<3><<<dim3(32, 32), 256, HSMEM_BYTES>>>(xh, w1h, nullptr, nullptr, xzh,
                                       ROWS, 2 * DINNER, DMODEL,
                                       DMODEL, DMODEL, 2 * DINNER);
    // 2) u = silu(causal_conv(xb) + b)   [4096, 2048]  (fp16)
    conv_silu_kernel<<<(ROWS * DINNER) / 256, 256>>>(xzh, conv_w, conv_b, uh);
    // 3) x_dbl = u @ x_proj_w^T          [4096, 160]  split-K x4 + reduce
    hgemm_nt<4><<<dim3(2, 32, KSPLIT), 256, HSMEM_BYTES>>>(uh, w2h, xp4, nullptr, nullptr,
                                       ROWS, XPROJ_N, DINNER / KSPLIT,
                                       DINNER, DINNER, XPROJ_N);
    xproj_reduce<<<(XPN / 4 + 255) / 256, 256>>>(xp4, xdbl, dtin_h);
    // 4) dt = softplus(dt_in @ dt_proj_w^T + b)   [4096, 2048]
    hgemm_nt<1><<<dim3(16, 32), 256, HSMEM_BYTES>>>(dtin_h, w3h, dtb, dt_proj_b, nullptr,
                                       ROWS, DINNER, DTRANK,
                                       DTRANK, DTRANK, DINNER);
    // 5) chunked selective scan -> y (fp16)
    scan_pass1<<<dim3(DINNER / 128, CHUNKS, BATCH), 128>>>(uh, dtb, xdbl, A_log, hp, Ss);
    scan_combine<<<dim3(DINNER / 128, DSTATE, BATCH), 128>>>(A_log, Ss, hp, hs);
    scan_pass2<<<dim3(DINNER / 128, CHUNKS, BATCH), 128>>>(uh, dtb, xdbl, xzh, A_log, Dp, hs, yh);
    // 6) out = y @ out_proj_w^T          [4096, 1024]
    hgemm_nt<0><<<dim3(8, 32), 256, HSMEM_BYTES>>>(yh, w4h, out, nullptr, nullptr,
                                      ROWS, DMODEL, DINNER,
                                      DINNER, DINNER, DMODEL);
}